// round 4
// baseline (speedup 1.0000x reference)
#include <cuda_runtime.h>

// Problem constants (fixed shapes from reference setup_inputs)
#define TOKENS (8*128*256)       // 262144
#define CIN 15
#define DD 128
#define STAT_TILE 512
#define STAT_BLOCKS (TOKENS/STAT_TILE)   // 512
#define MAIN_TILE 64
#define MAIN_BLOCKS (TOKENS/MAIN_TILE)   // 4096
#define HR_STRIDE 68                     // padded (mult of 4, +4 vs 64 to break conflicts)

// Deterministic two-stage reduction scratch (no atomics -> bitwise replay-stable)
__device__ float g_part[STAT_BLOCKS * 258];   // [block][sum(128) | sumsq(128) | cnt | pad]
__device__ float g_A[DD];
__device__ float g_C[DD];

// ---------------- Pass A: masked per-channel sum / sumsq of h = diff@W1 + b1 ----------------
__global__ void k_stats(const float* __restrict__ diff, const int* __restrict__ mask,
                        const float* __restrict__ W1, const float* __restrict__ b1) {
    extern __shared__ float s[];
    float* diffS = s;                         // 512*15
    float* W1s   = diffS + STAT_TILE*CIN;     // 15*128
    float* maskS = W1s + CIN*DD;              // 512
    float* sumS  = maskS + STAT_TILE;         // 256
    float* sqS   = sumS + 256;                // 256

    int tid = threadIdx.x;
    int tok0 = blockIdx.x * STAT_TILE;
    for (int i = tid; i < STAT_TILE*CIN; i += 256) diffS[i] = diff[(size_t)tok0*CIN + i];
    for (int i = tid; i < CIN*DD; i += 256) W1s[i] = W1[i];
    for (int i = tid; i < STAT_TILE; i += 256) maskS[i] = mask[tok0 + i] ? 1.0f : 0.0f;
    __syncthreads();

    int d = tid & (DD-1);
    int half = tid >> 7;                      // 0 or 1
    float bb = b1[d];
    float sum = 0.f, sq = 0.f;
    for (int i = 0; i < STAT_TILE/2; i++) {
        int t = half + 2*i;
        if (maskS[t] != 0.f) {                // warp-uniform branch
            float h = bb;
            #pragma unroll
            for (int c = 0; c < CIN; c++) h += diffS[t*CIN + c] * W1s[c*DD + d];
            sum += h; sq += h*h;
        }
    }
    sumS[tid] = sum; sqS[tid] = sq;
    __syncthreads();
    if (tid < DD) {
        g_part[blockIdx.x*258 + tid]       = sumS[tid] + sumS[tid + 128];
        g_part[blockIdx.x*258 + 128 + tid] = sqS[tid]  + sqS[tid + 128];
    }
    if (tid == 0) {
        float c = 0.f;
        for (int i = 0; i < STAT_TILE; i++) c += maskS[i];
        g_part[blockIdx.x*258 + 256] = c;
    }
}

// ---------------- Pass B: finalize BN into affine A[d]*h + C[d] (b1 folded in) ----------------
__global__ void k_final(const float* __restrict__ b1, const float* __restrict__ gamma,
                        const float* __restrict__ beta) {
    int d = threadIdx.x;
    float sum = 0.f, sq = 0.f, cnt = 0.f;
    for (int b = 0; b < STAT_BLOCKS; b++) {
        const float* p = &g_part[b*258];
        sum += p[d]; sq += p[128 + d]; cnt += p[256];
    }
    if (cnt < 1.f) cnt = 1.f;
    float mean = sum / cnt;
    float var  = fmaxf(sq / cnt - mean*mean, 0.f);
    float A = gamma[d] * rsqrtf(var + 1e-5f);
    g_A[d] = A;
    g_C[d] = beta[d] + (b1[d] - mean) * A;    // h_lin*A + C == (h+b1-mean)*inv*gamma+beta
}

// ---------------- Pass C: recompute GEMM1, BN+ReLU, GEMM2, masked store ----------------
__global__ void __launch_bounds__(256) k_main(
        const float* __restrict__ diff, const int* __restrict__ mask,
        const float* __restrict__ W1, const float* __restrict__ W2,
        const float* __restrict__ b2, float* __restrict__ out) {
    extern __shared__ float s[];
    float* W2s  = s;                          // 128*128  (64 KB)
    float* hrS  = W2s + DD*DD;                // 128*68   [d][t], padded
    float* W1s  = hrS + DD*HR_STRIDE;         // 15*128
    float* As   = W1s + CIN*DD;               // 128
    float* Cs   = As + DD;                    // 128
    float* b2S  = Cs + DD;                    // 128
    float* diffS= b2S + DD;                   // 64*15
    float* mS   = diffS + MAIN_TILE*CIN;      // 64

    int tid = threadIdx.x;
    int tok0 = blockIdx.x * MAIN_TILE;

    for (int i = tid; i < DD*DD/4; i += 256)
        ((float4*)W2s)[i] = ((const float4*)W2)[i];
    for (int i = tid; i < CIN*DD; i += 256) W1s[i] = W1[i];
    if (tid < DD) { As[tid] = g_A[tid]; Cs[tid] = g_C[tid]; b2S[tid] = b2[tid]; }
    for (int i = tid; i < MAIN_TILE*CIN; i += 256) diffS[i] = diff[(size_t)tok0*CIN + i];
    if (tid < MAIN_TILE) mS[tid] = mask[tok0 + tid] ? 1.0f : 0.0f;
    __syncthreads();

    // GEMM1 + folded BN + ReLU -> hrS[d][t]  (thread: one token, 32 channels)
    {
        int t  = tid & 63;
        int dg = tid >> 6;                    // 0..3
        float dr[CIN];
        #pragma unroll
        for (int c = 0; c < CIN; c++) dr[c] = diffS[t*CIN + c];
        #pragma unroll
        for (int j = 0; j < 32; j++) {
            int d = dg*32 + j;
            float h = 0.f;
            #pragma unroll
            for (int c = 0; c < CIN; c++) h += dr[c] * W1s[c*DD + d];   // W1 broadcast
            h = h * As[d] + Cs[d];
            hrS[d*HR_STRIDE + t] = fmaxf(h, 0.f);
        }
    }
    __syncthreads();

    // GEMM2: thread computes 8 tokens x 4 output channels
    int eg = tid & 31;                        // e = eg*4
    int t0 = (tid >> 5) * 8;
    float acc[8][4];
    #pragma unroll
    for (int k = 0; k < 8; k++)
        #pragma unroll
        for (int j = 0; j < 4; j++) acc[k][j] = 0.f;

    #pragma unroll 4
    for (int d = 0; d < DD; d++) {
        float4 w  = *(const float4*)&W2s[d*DD + eg*4];
        float4 h0 = *(const float4*)&hrS[d*HR_STRIDE + t0];       // broadcast in warp
        float4 h1 = *(const float4*)&hrS[d*HR_STRIDE + t0 + 4];
        float hv[8] = {h0.x,h0.y,h0.z,h0.w,h1.x,h1.y,h1.z,h1.w};
        #pragma unroll
        for (int k = 0; k < 8; k++) {
            acc[k][0] += hv[k]*w.x;
            acc[k][1] += hv[k]*w.y;
            acc[k][2] += hv[k]*w.z;
            acc[k][3] += hv[k]*w.w;
        }
    }
    float4 bb = *(const float4*)&b2S[eg*4];
    #pragma unroll
    for (int k = 0; k < 8; k++) {
        float m = mS[t0 + k];
        float4 r;
        r.x = (acc[k][0] + bb.x) * m;
        r.y = (acc[k][1] + bb.y) * m;
        r.z = (acc[k][2] + bb.z) * m;
        r.w = (acc[k][3] + bb.w) * m;
        *(float4*)&out[(size_t)(tok0 + t0 + k)*DD + eg*4] = r;
    }
}

// Optional second output: mask echoed back (only if out_size says so)
__global__ void k_mask_out(const int* __restrict__ mask, float* __restrict__ out_tail) {
    int i = blockIdx.x*256 + threadIdx.x;
    if (i < TOKENS) out_tail[i] = mask[i] ? 1.0f : 0.0f;
}

#define SMEM_STAT ((STAT_TILE*CIN + CIN*DD + STAT_TILE + 256 + 256) * 4)
#define SMEM_MAIN ((DD*DD + DD*HR_STRIDE + CIN*DD + 3*DD + MAIN_TILE*CIN + MAIN_TILE) * 4)

extern "C" void kernel_launch(void* const* d_in, const int* in_sizes, int n_in,
                              void* d_out, int out_size) {
    const float* diff  = (const float*)d_in[0];
    const int*   mask  = (const int*)d_in[1];
    const float* W1    = (const float*)d_in[2];
    const float* b1    = (const float*)d_in[3];
    const float* gamma = (const float*)d_in[4];
    const float* beta  = (const float*)d_in[5];
    const float* W2    = (const float*)d_in[6];
    const float* b2    = (const float*)d_in[7];
    float* out = (float*)d_out;

    cudaFuncSetAttribute(k_main,  cudaFuncAttributeMaxDynamicSharedMemorySize, SMEM_MAIN);
    cudaFuncSetAttribute(k_stats, cudaFuncAttributeMaxDynamicSharedMemorySize, SMEM_STAT);

    k_stats<<<STAT_BLOCKS, 256, SMEM_STAT>>>(diff, mask, W1, b1);
    k_final<<<1, DD>>>(b1, gamma, beta);
    k_main<<<MAIN_BLOCKS, 256, SMEM_MAIN>>>(diff, mask, W1, W2, b2, out);

    if (out_size > TOKENS*DD) {
        // harness wants (out, mask) concatenated; echo mask as float 0/1
        k_mask_out<<<(TOKENS + 255)/256, 256>>>(mask, out + (size_t)TOKENS*DD);
    }
}

// round 11
// speedup vs baseline: 2.2100x; 2.2100x over previous
#include <cuda_runtime.h>
#include <cuda_bf16.h>
#include <cstdint>

// ---------------- problem constants ----------------
#define TOKENS (8*128*256)        // 262144
#define CIN 15
#define DD 128
#define PBB 272                   // bf16 row pitch bytes (136 elems) -> conflict-free ldmatrix

// ---------------- smem layout (bytes) ----------------
#define OFF_W2HI 0                // 128 x 136 bf16 = 34816
#define OFF_W2LO 34816
#define OFF_HHI  69632            // h hi  (128 tok x 136)
#define OFF_HLO  104448           // h lo
#define OFF_DIFF 139264           // 128*15 f32 = 7680
#define OFF_W1   146944           // 15*128 f32 = 7680
#define OFF_MS   154624           // 128 f32
#define OFF_B2   155136
#define OFF_AS   155648
#define OFF_CS   156160
#define SMEM_MAIN 156672
#define OFF_STAGE OFF_HHI         // overlays h after MMA (67584 <= 69632)
#define STG_W 132                 // stage row stride (floats)

__device__ __forceinline__ uint32_t smem_u32(const void* p) {
    uint32_t a;
    asm("{ .reg .u64 t; cvta.to.shared.u64 t, %1; cvt.u32.u64 %0, t; }" : "=r"(a) : "l"(p));
    return a;
}
__device__ __forceinline__ void ldm_x4(uint32_t* r, uint32_t addr) {
    asm volatile("ldmatrix.sync.aligned.m8n8.x4.shared.b16 {%0,%1,%2,%3}, [%4];"
                 : "=r"(r[0]), "=r"(r[1]), "=r"(r[2]), "=r"(r[3]) : "r"(addr));
}
__device__ __forceinline__ void ldm_x4_t(uint32_t* r, uint32_t addr) {
    asm volatile("ldmatrix.sync.aligned.m8n8.x4.trans.shared.b16 {%0,%1,%2,%3}, [%4];"
                 : "=r"(r[0]), "=r"(r[1]), "=r"(r[2]), "=r"(r[3]) : "r"(addr));
}
__device__ __forceinline__ void mma_bf16(float* d, const uint32_t* a, uint32_t b0, uint32_t b1) {
    asm volatile("mma.sync.aligned.m16n8k16.row.col.f32.bf16.bf16.f32 "
                 "{%0,%1,%2,%3}, {%4,%5,%6,%7}, {%8,%9}, {%0,%1,%2,%3};"
                 : "+f"(d[0]), "+f"(d[1]), "+f"(d[2]), "+f"(d[3])
                 : "r"(a[0]), "r"(a[1]), "r"(a[2]), "r"(a[3]), "r"(b0), "r"(b1));
}

// ---------------- global scratch ----------------
#define NSTAT 136                      // su[15] + S_upper[120] + cnt
#define STAT_BLOCKS 512
__device__ float g_p2[STAT_BLOCKS * NSTAT];
__device__ float g_A[DD];
__device__ float g_C[DD];

// ================= Pass A: masked 2nd-moment matrix of u=(diff,1) =================
__global__ void __launch_bounds__(128) k_stats2(const float* __restrict__ diff,
                                                const int* __restrict__ mask) {
    __shared__ float red[4 * NSTAT];
    int tid = threadIdx.x, lid = tid & 31, w = tid >> 5;
    int tok0 = blockIdx.x * (TOKENS / STAT_BLOCKS);   // 512 tokens/block

    float su[CIN]; float S[120]; float cnt = 0.f;
    #pragma unroll
    for (int i = 0; i < CIN; i++) su[i] = 0.f;
    #pragma unroll
    for (int i = 0; i < 120; i++) S[i] = 0.f;

    for (int r = 0; r < 4; r++) {
        int t = tok0 + r * 128 + tid;
        if (mask[t]) {
            float v[CIN];
            #pragma unroll
            for (int c = 0; c < CIN; c++) v[c] = diff[(size_t)t * CIN + c];
            cnt += 1.f;
            int idx = 0;
            #pragma unroll
            for (int i = 0; i < CIN; i++) {
                su[i] += v[i];
                #pragma unroll
                for (int j = i; j < CIN; j++) { S[idx] += v[i] * v[j]; idx++; }
            }
        }
    }
    #pragma unroll
    for (int o = 16; o; o >>= 1) {
        #pragma unroll
        for (int i = 0; i < CIN; i++) su[i] += __shfl_down_sync(0xffffffffu, su[i], o);
        #pragma unroll
        for (int i = 0; i < 120; i++) S[i] += __shfl_down_sync(0xffffffffu, S[i], o);
        cnt += __shfl_down_sync(0xffffffffu, cnt, o);
    }
    if (lid == 0) {
        #pragma unroll
        for (int i = 0; i < CIN; i++) red[w * NSTAT + i] = su[i];
        #pragma unroll
        for (int i = 0; i < 120; i++) red[w * NSTAT + CIN + i] = S[i];
        red[w * NSTAT + 135] = cnt;
    }
    __syncthreads();
    // FIX (R6 root cause): NSTAT=136 > blockDim=128, entries 128..135 (incl. cnt)
    // were never written. Strided loop covers all NSTAT entries.
    for (int i = tid; i < NSTAT; i += 128)
        g_p2[blockIdx.x * NSTAT + i] =
            red[i] + red[NSTAT + i] + red[2 * NSTAT + i] + red[3 * NSTAT + i];
}

// ================= Pass B: finalize BN affine =================
__global__ void __launch_bounds__(256) k_final2(const float* __restrict__ W1,
                                                const float* __restrict__ b1,
                                                const float* __restrict__ gamma,
                                                const float* __restrict__ beta) {
    __shared__ float tot[NSTAT];
    __shared__ float Sf[CIN][CIN];
    __shared__ float suS[CIN];
    __shared__ float cntS;
    int tid = threadIdx.x;
    if (tid < NSTAT) {
        float s = 0.f;
        for (int b = 0; b < STAT_BLOCKS; b++) s += g_p2[b * NSTAT + tid];
        tot[tid] = s;
    }
    __syncthreads();
    if (tid < CIN * CIN) {
        int i = tid / CIN, j = tid % CIN;
        int a = i < j ? i : j, b = i < j ? j : i;
        Sf[i][j] = tot[CIN + a * CIN - (a * (a - 1)) / 2 + (b - a)];
    }
    if (tid < CIN) suS[tid] = tot[tid];
    if (tid == 0) cntS = tot[135];
    __syncthreads();
    if (tid < DD) {
        int d = tid;
        float w[CIN];
        #pragma unroll
        for (int c = 0; c < CIN; c++) w[c] = W1[c * DD + d];
        float sh = 0.f;
        #pragma unroll
        for (int c = 0; c < CIN; c++) sh += suS[c] * w[c];
        float q = 0.f;
        #pragma unroll
        for (int i = 0; i < CIN; i++) {
            float acc = 0.f;
            #pragma unroll
            for (int j = 0; j < CIN; j++) acc += Sf[i][j] * w[j];
            q += w[i] * acc;
        }
        float cnt = fmaxf(cntS, 1.f);
        float bb = b1[d];
        float mean = (sh + cnt * bb) / cnt;
        float sum2 = q + 2.f * bb * sh + cnt * bb * bb;
        float var = fmaxf(sum2 / cnt - mean * mean, 0.f);
        float A = gamma[d] * rsqrtf(var + 1e-5f);
        g_A[d] = A;
        g_C[d] = beta[d] + (bb - mean) * A;
    }
}

// ================= Pass C: scalar GEMM1 + split-bf16 HMMA GEMM2 =================
__global__ void __launch_bounds__(256, 1) k_main(
        const float* __restrict__ diff, const int* __restrict__ mask,
        const float* __restrict__ W1, const float* __restrict__ W2,
        const float* __restrict__ b2, float* __restrict__ out) {
    extern __shared__ char sm[];
    float* smf = (float*)sm;
    uint32_t smb = smem_u32(sm);
    int tid = threadIdx.x, lid = tid & 31, wid = tid >> 5;
    int tok0 = blockIdx.x * DD;

    // --- load & split W2 into hi/lo bf16, [d][e] row-major pitch 136 ---
    for (int idx = tid; idx < DD * DD; idx += 256) {
        int d = idx >> 7, e = idx & 127;
        float v = W2[idx];
        __nv_bfloat16 vh = __float2bfloat16(v);
        __nv_bfloat16 vl = __float2bfloat16(v - __bfloat162float(vh));
        *(__nv_bfloat16*)(sm + OFF_W2HI + d * PBB + e * 2) = vh;
        *(__nv_bfloat16*)(sm + OFF_W2LO + d * PBB + e * 2) = vl;
    }
    for (int i = tid; i < DD * CIN; i += 256) {
        smf[OFF_DIFF/4 + i] = diff[(size_t)tok0 * CIN + i];
        smf[OFF_W1/4 + i]   = W1[i];
    }
    if (tid < DD) {
        smf[OFF_MS/4 + tid] = mask[tok0 + tid] ? 1.0f : 0.0f;
        smf[OFF_B2/4 + tid] = b2[tid];
        smf[OFF_AS/4 + tid] = g_A[tid];
        smf[OFF_CS/4 + tid] = g_C[tid];
    }
    __syncthreads();

    // --- GEMM1 (scalar fp32) + BN + ReLU -> split bf16 hi/lo to smem ---
    {
        int t  = (wid & 3) * 32 + lid;          // token 0..127 (two warp groups duplicate tokens)
        int cb = (wid < 4) ? 0 : 64;            // channel half
        float dr[CIN];
        #pragma unroll
        for (int c = 0; c < CIN; c++) dr[c] = smf[OFF_DIFF/4 + t * CIN + c];
        float h[64];
        #pragma unroll
        for (int j = 0; j < 64; j++) h[j] = 0.f;
        #pragma unroll
        for (int c = 0; c < CIN; c++) {
            float dv = dr[c];
            #pragma unroll
            for (int j4 = 0; j4 < 16; j4++) {
                float4 wv = *(const float4*)&smf[OFF_W1/4 + c * DD + cb + j4 * 4];
                h[j4*4+0] += dv * wv.x; h[j4*4+1] += dv * wv.y;
                h[j4*4+2] += dv * wv.z; h[j4*4+3] += dv * wv.w;
            }
        }
        #pragma unroll
        for (int p = 0; p < 32; p++) {
            int d = cb + 2 * p;
            float a = fmaxf(h[2*p]   * smf[OFF_AS/4 + d]     + smf[OFF_CS/4 + d],     0.f);
            float b = fmaxf(h[2*p+1] * smf[OFF_AS/4 + d + 1] + smf[OFF_CS/4 + d + 1], 0.f);
            __nv_bfloat16 ah = __float2bfloat16(a);
            __nv_bfloat16 al = __float2bfloat16(a - __bfloat162float(ah));
            __nv_bfloat16 bh = __float2bfloat16(b);
            __nv_bfloat16 bl = __float2bfloat16(b - __bfloat162float(bh));
            uint32_t hiw = ((uint32_t)__bfloat16_as_ushort(bh) << 16) | __bfloat16_as_ushort(ah);
            uint32_t low = ((uint32_t)__bfloat16_as_ushort(bl) << 16) | __bfloat16_as_ushort(al);
            *(uint32_t*)(sm + OFF_HHI + t * PBB + d * 2) = hiw;
            *(uint32_t*)(sm + OFF_HLO + t * PBB + d * 2) = low;
        }
    }
    __syncthreads();

    // --- GEMM2: warp = 16 tokens x 128 channels, K=128, 3 split products ---
    float acc[16][4];
    #pragma unroll
    for (int n = 0; n < 16; n++)
        #pragma unroll
        for (int j = 0; j < 4; j++) acc[n][j] = 0.f;

    {
        int t0 = wid * 16;
        int g = lid >> 3, i8 = lid & 7;
        uint32_t aHi = smb + OFF_HHI + (uint32_t)(t0 + i8 + ((g & 1) << 3)) * PBB + ((g >> 1) << 4);
        uint32_t aLo = aHi + (OFF_HLO - OFF_HHI);
        uint32_t bHi = smb + OFF_W2HI + (uint32_t)(i8 + ((g & 1) << 3)) * PBB + ((g >> 1) << 4);
        uint32_t bLo = bHi + (OFF_W2LO - OFF_W2HI);

        #pragma unroll 2
        for (int kk = 0; kk < 8; kk++) {
            uint32_t ah[4], al[4];
            ldm_x4(ah, aHi + kk * 32);
            ldm_x4(al, aLo + kk * 32);
            uint32_t bkoff = (uint32_t)kk * 16 * PBB;
            #pragma unroll
            for (int nb2 = 0; nb2 < 8; nb2++) {
                uint32_t bh[4], bl[4];
                ldm_x4_t(bh, bHi + bkoff + nb2 * 32);
                ldm_x4_t(bl, bLo + bkoff + nb2 * 32);
                int n0 = nb2 * 2;
                mma_bf16(acc[n0],     ah, bh[0], bh[1]);
                mma_bf16(acc[n0],     al, bh[0], bh[1]);
                mma_bf16(acc[n0],     ah, bl[0], bl[1]);
                mma_bf16(acc[n0 + 1], ah, bh[2], bh[3]);
                mma_bf16(acc[n0 + 1], al, bh[2], bh[3]);
                mma_bf16(acc[n0 + 1], ah, bl[2], bl[3]);
            }
        }
    }
    __syncthreads();   // all warps done reading h -> safe to overlay stage

    // --- epilogue: bias + mask -> stage smem -> coalesced float4 stores ---
    {
        int t0 = wid * 16;
        int row = t0 + (lid >> 2);
        float m1 = smf[OFF_MS/4 + row];
        float m2 = smf[OFF_MS/4 + row + 8];
        #pragma unroll
        for (int nt = 0; nt < 16; nt++) {
            int col = nt * 8 + (lid & 3) * 2;
            float b0 = smf[OFF_B2/4 + col], b1v = smf[OFF_B2/4 + col + 1];
            smf[OFF_STAGE/4 + row * STG_W + col]           = (acc[nt][0] + b0)  * m1;
            smf[OFF_STAGE/4 + row * STG_W + col + 1]       = (acc[nt][1] + b1v) * m1;
            smf[OFF_STAGE/4 + (row + 8) * STG_W + col]     = (acc[nt][2] + b0)  * m2;
            smf[OFF_STAGE/4 + (row + 8) * STG_W + col + 1] = (acc[nt][3] + b1v) * m2;
        }
    }
    __syncthreads();
    #pragma unroll
    for (int i = 0; i < 16; i++) {
        int idx = tid + i * 256;
        int token = idx >> 5, c4 = idx & 31;
        float4 v = *(const float4*)&smf[OFF_STAGE/4 + token * STG_W + c4 * 4];
        *(float4*)&out[(size_t)(tok0 + token) * DD + c4 * 4] = v;
    }
}

// optional second output: echo mask as float
__global__ void k_mask_out(const int* __restrict__ mask, float* __restrict__ out_tail) {
    int i = blockIdx.x * 256 + threadIdx.x;
    if (i < TOKENS) out_tail[i] = mask[i] ? 1.0f : 0.0f;
}

extern "C" void kernel_launch(void* const* d_in, const int* in_sizes, int n_in,
                              void* d_out, int out_size) {
    const float* diff  = (const float*)d_in[0];
    const int*   mask  = (const int*)d_in[1];
    const float* W1    = (const float*)d_in[2];
    const float* b1    = (const float*)d_in[3];
    const float* gamma = (const float*)d_in[4];
    const float* beta  = (const float*)d_in[5];
    const float* W2    = (const float*)d_in[6];
    const float* b2    = (const float*)d_in[7];
    float* out = (float*)d_out;

    cudaFuncSetAttribute(k_main, cudaFuncAttributeMaxDynamicSharedMemorySize, SMEM_MAIN);

    k_stats2<<<STAT_BLOCKS, 128>>>(diff, mask);
    k_final2<<<1, 256>>>(W1, b1, gamma, beta);
    k_main<<<TOKENS / DD, 256, SMEM_MAIN>>>(diff, mask, W1, W2, b2, out);

    if (out_size > TOKENS * DD) {
        k_mask_out<<<(TOKENS + 255) / 256, 256>>>(mask, out + (size_t)TOKENS * DD);
    }
}

// round 12
// speedup vs baseline: 2.9982x; 1.3566x over previous
#include <cuda_runtime.h>
#include <cuda_bf16.h>
#include <cstdint>

// ---------------- problem constants ----------------
#define TOKENS (8*128*256)        // 262144
#define CIN 15
#define DD 128
#define NTILES (TOKENS/DD)        // 2048 token tiles
#define PBB 272                   // bf16 row pitch bytes (136 elems) -> conflict-free ldmatrix

// ---------------- smem layout (bytes) ----------------
#define OFF_W2HI 0                // 128 x 136 bf16 = 34816
#define OFF_W2LO 34816
#define OFF_HHI  69632            // h hi  (128 tok x 136)
#define OFF_HLO  104448           // h lo
#define OFF_DIFF 139264           // 128*15 f32 = 7680
#define OFF_W1   146944           // 15*128 f32 = 7680
#define OFF_MS   154624           // 128 f32
#define OFF_B2   155136
#define OFF_AS   155648
#define OFF_CS   156160
#define SMEM_MAIN 156672
#define OFF_STAGE OFF_HHI         // overlays h after MMA (67584 <= 69632, ends 137216 < OFF_DIFF)
#define STG_W 132                 // stage row stride (floats)

__device__ __forceinline__ uint32_t smem_u32(const void* p) {
    uint32_t a;
    asm("{ .reg .u64 t; cvta.to.shared.u64 t, %1; cvt.u32.u64 %0, t; }" : "=r"(a) : "l"(p));
    return a;
}
__device__ __forceinline__ void ldm_x4(uint32_t* r, uint32_t addr) {
    asm volatile("ldmatrix.sync.aligned.m8n8.x4.shared.b16 {%0,%1,%2,%3}, [%4];"
                 : "=r"(r[0]), "=r"(r[1]), "=r"(r[2]), "=r"(r[3]) : "r"(addr));
}
__device__ __forceinline__ void ldm_x4_t(uint32_t* r, uint32_t addr) {
    asm volatile("ldmatrix.sync.aligned.m8n8.x4.trans.shared.b16 {%0,%1,%2,%3}, [%4];"
                 : "=r"(r[0]), "=r"(r[1]), "=r"(r[2]), "=r"(r[3]) : "r"(addr));
}
__device__ __forceinline__ void mma_bf16(float* d, const uint32_t* a, uint32_t b0, uint32_t b1) {
    asm volatile("mma.sync.aligned.m16n8k16.row.col.f32.bf16.bf16.f32 "
                 "{%0,%1,%2,%3}, {%4,%5,%6,%7}, {%8,%9}, {%0,%1,%2,%3};"
                 : "+f"(d[0]), "+f"(d[1]), "+f"(d[2]), "+f"(d[3])
                 : "r"(a[0]), "r"(a[1]), "r"(a[2]), "r"(a[3]), "r"(b0), "r"(b1));
}

// ---------------- global scratch ----------------
#define NSTAT 136                      // su[15] + S_upper[120] + cnt
#define STAT_BLOCKS 512
__device__ float g_p2[STAT_BLOCKS * NSTAT];
__device__ float g_A[DD];
__device__ float g_C[DD];

// ================= Pass A: masked 2nd-moment matrix of u=(diff,1) =================
__global__ void __launch_bounds__(128) k_stats2(const float* __restrict__ diff,
                                                const int* __restrict__ mask) {
    __shared__ float red[4 * NSTAT];
    int tid = threadIdx.x, lid = tid & 31, w = tid >> 5;
    int tok0 = blockIdx.x * (TOKENS / STAT_BLOCKS);   // 512 tokens/block

    float su[CIN]; float S[120]; float cnt = 0.f;
    #pragma unroll
    for (int i = 0; i < CIN; i++) su[i] = 0.f;
    #pragma unroll
    for (int i = 0; i < 120; i++) S[i] = 0.f;

    for (int r = 0; r < 4; r++) {
        int t = tok0 + r * 128 + tid;
        if (mask[t]) {
            float v[CIN];
            #pragma unroll
            for (int c = 0; c < CIN; c++) v[c] = diff[(size_t)t * CIN + c];
            cnt += 1.f;
            int idx = 0;
            #pragma unroll
            for (int i = 0; i < CIN; i++) {
                su[i] += v[i];
                #pragma unroll
                for (int j = i; j < CIN; j++) { S[idx] += v[i] * v[j]; idx++; }
            }
        }
    }
    #pragma unroll
    for (int o = 16; o; o >>= 1) {
        #pragma unroll
        for (int i = 0; i < CIN; i++) su[i] += __shfl_down_sync(0xffffffffu, su[i], o);
        #pragma unroll
        for (int i = 0; i < 120; i++) S[i] += __shfl_down_sync(0xffffffffu, S[i], o);
        cnt += __shfl_down_sync(0xffffffffu, cnt, o);
    }
    if (lid == 0) {
        #pragma unroll
        for (int i = 0; i < CIN; i++) red[w * NSTAT + i] = su[i];
        #pragma unroll
        for (int i = 0; i < 120; i++) red[w * NSTAT + CIN + i] = S[i];
        red[w * NSTAT + 135] = cnt;
    }
    __syncthreads();
    for (int i = tid; i < NSTAT; i += 128)
        g_p2[blockIdx.x * NSTAT + i] =
            red[i] + red[NSTAT + i] + red[2 * NSTAT + i] + red[3 * NSTAT + i];
}

// ================= Pass B: finalize BN affine (parallel 4-way reduction) =================
__global__ void __launch_bounds__(544) k_final2(const float* __restrict__ W1,
                                                const float* __restrict__ b1,
                                                const float* __restrict__ gamma,
                                                const float* __restrict__ beta) {
    __shared__ float part[4 * NSTAT];
    __shared__ float tot[NSTAT];
    __shared__ float Sf[CIN][CIN];
    __shared__ float suS[CIN];
    __shared__ float cntS;
    int tid = threadIdx.x;
    {
        int grp = tid / NSTAT, j = tid - grp * NSTAT;   // 4 groups x 136
        float s = 0.f;
        for (int b = grp; b < STAT_BLOCKS; b += 4) s += g_p2[b * NSTAT + j];
        part[grp * NSTAT + j] = s;
    }
    __syncthreads();
    if (tid < NSTAT)
        tot[tid] = part[tid] + part[NSTAT + tid] + part[2 * NSTAT + tid] + part[3 * NSTAT + tid];
    __syncthreads();
    if (tid < CIN * CIN) {
        int i = tid / CIN, j = tid % CIN;
        int a = i < j ? i : j, b = i < j ? j : i;
        Sf[i][j] = tot[CIN + a * CIN - (a * (a - 1)) / 2 + (b - a)];
    }
    if (tid < CIN) suS[tid] = tot[tid];
    if (tid == 0) cntS = tot[135];
    __syncthreads();
    if (tid < DD) {
        int d = tid;
        float w[CIN];
        #pragma unroll
        for (int c = 0; c < CIN; c++) w[c] = W1[c * DD + d];
        float sh = 0.f;
        #pragma unroll
        for (int c = 0; c < CIN; c++) sh += suS[c] * w[c];
        float q = 0.f;
        #pragma unroll
        for (int i = 0; i < CIN; i++) {
            float acc = 0.f;
            #pragma unroll
            for (int j = 0; j < CIN; j++) acc += Sf[i][j] * w[j];
            q += w[i] * acc;
        }
        float cnt = fmaxf(cntS, 1.f);
        float bb = b1[d];
        float mean = (sh + cnt * bb) / cnt;
        float sum2 = q + 2.f * bb * sh + cnt * bb * bb;
        float var = fmaxf(sum2 / cnt - mean * mean, 0.f);
        float A = gamma[d] * rsqrtf(var + 1e-5f);
        g_A[d] = A;
        g_C[d] = beta[d] + (bb - mean) * A;
    }
}

// ========== Pass C (persistent): scalar GEMM1 + split-bf16 HMMA GEMM2 ==========
__global__ void __launch_bounds__(256, 1) k_main(
        const float* __restrict__ diff, const int* __restrict__ mask,
        const float* __restrict__ W1, const float* __restrict__ W2,
        const float* __restrict__ b2, float* __restrict__ out, int do_tail) {
    extern __shared__ char sm[];
    float* smf = (float*)sm;
    uint32_t smb = smem_u32(sm);
    int tid = threadIdx.x, lid = tid & 31, wid = tid >> 5;

    // --- once per CTA: load & split W2 into hi/lo bf16, load W1/A/C/b2 ---
    for (int idx = tid; idx < DD * DD; idx += 256) {
        int d = idx >> 7, e = idx & 127;
        float v = W2[idx];
        __nv_bfloat16 vh = __float2bfloat16(v);
        __nv_bfloat16 vl = __float2bfloat16(v - __bfloat162float(vh));
        *(__nv_bfloat16*)(sm + OFF_W2HI + d * PBB + e * 2) = vh;
        *(__nv_bfloat16*)(sm + OFF_W2LO + d * PBB + e * 2) = vl;
    }
    for (int i = tid; i < DD * CIN; i += 256) smf[OFF_W1/4 + i] = W1[i];
    if (tid < DD) {
        smf[OFF_B2/4 + tid] = b2[tid];
        smf[OFF_AS/4 + tid] = g_A[tid];
        smf[OFF_CS/4 + tid] = g_C[tid];
    }

    // warp tile geometry: 32 tokens x 64 channels per warp
    int wt = wid >> 1;                 // 0..3 token quarter
    int c0 = (wid & 1) * 64;           // channel half base
    int t0w = wt * 32;
    int g = lid >> 3, i8 = lid & 7;
    uint32_t aHi0 = smb + OFF_HHI + (uint32_t)(t0w + i8 + ((g & 1) << 3)) * PBB + ((g >> 1) << 4);
    uint32_t aHi1 = aHi0 + 16 * PBB;
    uint32_t bBase = smb + OFF_W2HI + (uint32_t)(i8 + ((g & 1) << 3)) * PBB
                   + ((uint32_t)c0 << 1) + ((g >> 1) << 4);
    const uint32_t LO_A = OFF_HLO - OFF_HHI;
    const uint32_t LO_B = OFF_W2LO - OFF_W2HI;

    // --- persistent loop over token tiles ---
    for (int tile = blockIdx.x; tile < NTILES; tile += gridDim.x) {
        int tok0 = tile * DD;
        for (int i = tid; i < DD * CIN; i += 256)
            smf[OFF_DIFF/4 + i] = diff[(size_t)tok0 * CIN + i];
        if (tid < DD) smf[OFF_MS/4 + tid] = mask[tok0 + tid] ? 1.0f : 0.0f;
        __syncthreads();   // also protects stage (prev iter reads) before h writes

        // GEMM1 (scalar fp32) + BN + ReLU -> split bf16 hi/lo to smem
        {
            int t  = (wid & 3) * 32 + lid;
            int cb = (wid < 4) ? 0 : 64;
            float dr[CIN];
            #pragma unroll
            for (int c = 0; c < CIN; c++) dr[c] = smf[OFF_DIFF/4 + t * CIN + c];
            float h[64];
            #pragma unroll
            for (int j = 0; j < 64; j++) h[j] = 0.f;
            #pragma unroll
            for (int c = 0; c < CIN; c++) {
                float dv = dr[c];
                #pragma unroll
                for (int j4 = 0; j4 < 16; j4++) {
                    float4 wv = *(const float4*)&smf[OFF_W1/4 + c * DD + cb + j4 * 4];
                    h[j4*4+0] += dv * wv.x; h[j4*4+1] += dv * wv.y;
                    h[j4*4+2] += dv * wv.z; h[j4*4+3] += dv * wv.w;
                }
            }
            #pragma unroll
            for (int p = 0; p < 32; p++) {
                int d = cb + 2 * p;
                float a = fmaxf(h[2*p]   * smf[OFF_AS/4 + d]     + smf[OFF_CS/4 + d],     0.f);
                float b = fmaxf(h[2*p+1] * smf[OFF_AS/4 + d + 1] + smf[OFF_CS/4 + d + 1], 0.f);
                __nv_bfloat16 ah = __float2bfloat16(a);
                __nv_bfloat16 al = __float2bfloat16(a - __bfloat162float(ah));
                __nv_bfloat16 bh = __float2bfloat16(b);
                __nv_bfloat16 bl = __float2bfloat16(b - __bfloat162float(bh));
                uint32_t hiw = ((uint32_t)__bfloat16_as_ushort(bh) << 16) | __bfloat16_as_ushort(ah);
                uint32_t low = ((uint32_t)__bfloat16_as_ushort(bl) << 16) | __bfloat16_as_ushort(al);
                *(uint32_t*)(sm + OFF_HHI + t * PBB + d * 2) = hiw;
                *(uint32_t*)(sm + OFF_HLO + t * PBB + d * 2) = low;
            }
        }
        __syncthreads();

        // GEMM2: warp = 32 tokens x 64 channels, K=128, 3 split products
        float acc[2][8][4];
        #pragma unroll
        for (int mt = 0; mt < 2; mt++)
            #pragma unroll
            for (int n = 0; n < 8; n++)
                #pragma unroll
                for (int j = 0; j < 4; j++) acc[mt][n][j] = 0.f;

        #pragma unroll 2
        for (int kk = 0; kk < 8; kk++) {
            uint32_t ah[2][4], al[2][4];
            ldm_x4(ah[0], aHi0 + kk * 32);
            ldm_x4(al[0], aHi0 + LO_A + kk * 32);
            ldm_x4(ah[1], aHi1 + kk * 32);
            ldm_x4(al[1], aHi1 + LO_A + kk * 32);
            uint32_t bkoff = (uint32_t)kk * 16 * PBB;
            #pragma unroll
            for (int nb2 = 0; nb2 < 4; nb2++) {
                uint32_t bh[4], bl[4];
                ldm_x4_t(bh, bBase + bkoff + nb2 * 32);
                ldm_x4_t(bl, bBase + LO_B + bkoff + nb2 * 32);
                int n0 = nb2 * 2;
                #pragma unroll
                for (int mt = 0; mt < 2; mt++) {
                    mma_bf16(acc[mt][n0],     ah[mt], bh[0], bh[1]);
                    mma_bf16(acc[mt][n0],     al[mt], bh[0], bh[1]);
                    mma_bf16(acc[mt][n0],     ah[mt], bl[0], bl[1]);
                    mma_bf16(acc[mt][n0 + 1], ah[mt], bh[2], bh[3]);
                    mma_bf16(acc[mt][n0 + 1], al[mt], bh[2], bh[3]);
                    mma_bf16(acc[mt][n0 + 1], ah[mt], bl[2], bl[3]);
                }
            }
        }
        __syncthreads();   // all ldmatrix reads of h done -> safe to overlay stage

        // epilogue: bias + mask -> stage smem
        #pragma unroll
        for (int mt = 0; mt < 2; mt++) {
            int row = t0w + mt * 16 + (lid >> 2);
            float m1 = smf[OFF_MS/4 + row];
            float m2 = smf[OFF_MS/4 + row + 8];
            #pragma unroll
            for (int nt = 0; nt < 8; nt++) {
                int col = c0 + nt * 8 + (lid & 3) * 2;
                float b0 = smf[OFF_B2/4 + col], b1v = smf[OFF_B2/4 + col + 1];
                smf[OFF_STAGE/4 + row * STG_W + col]           = (acc[mt][nt][0] + b0)  * m1;
                smf[OFF_STAGE/4 + row * STG_W + col + 1]       = (acc[mt][nt][1] + b1v) * m1;
                smf[OFF_STAGE/4 + (row + 8) * STG_W + col]     = (acc[mt][nt][2] + b0)  * m2;
                smf[OFF_STAGE/4 + (row + 8) * STG_W + col + 1] = (acc[mt][nt][3] + b1v) * m2;
            }
        }
        __syncthreads();

        // coalesced float4 stores (+ fused mask-tail echo)
        #pragma unroll
        for (int i = 0; i < 16; i++) {
            int idx = tid + i * 256;
            int token = idx >> 5, c4 = idx & 31;
            float4 v = *(const float4*)&smf[OFF_STAGE/4 + token * STG_W + c4 * 4];
            *(float4*)&out[(size_t)(tok0 + token) * DD + c4 * 4] = v;
        }
        if (do_tail && tid < DD)
            out[(size_t)TOKENS * DD + tok0 + tid] = smf[OFF_MS/4 + tid];
    }
}

extern "C" void kernel_launch(void* const* d_in, const int* in_sizes, int n_in,
                              void* d_out, int out_size) {
    const float* diff  = (const float*)d_in[0];
    const int*   mask  = (const int*)d_in[1];
    const float* W1    = (const float*)d_in[2];
    const float* b1    = (const float*)d_in[3];
    const float* gamma = (const float*)d_in[4];
    const float* beta  = (const float*)d_in[5];
    const float* W2    = (const float*)d_in[6];
    const float* b2    = (const float*)d_in[7];
    float* out = (float*)d_out;
    int do_tail = (out_size > TOKENS * DD) ? 1 : 0;

    cudaFuncSetAttribute(k_main, cudaFuncAttributeMaxDynamicSharedMemorySize, SMEM_MAIN);

    k_stats2<<<STAT_BLOCKS, 128>>>(diff, mask);
    k_final2<<<1, 544>>>(W1, b1, gamma, beta);
    k_main<<<148, 256, SMEM_MAIN>>>(diff, mask, W1, W2, b2, out, do_tail);
}

// round 13
// speedup vs baseline: 3.6592x; 1.2205x over previous
#include <cuda_runtime.h>
#include <cuda_bf16.h>
#include <cstdint>

// ---------------- problem constants ----------------
#define TOKENS (8*128*256)        // 262144
#define CIN 15
#define DD 128
#define NTILES (TOKENS/DD)        // 2048 token tiles
#define PBB 272                   // h / W2 row pitch bytes (136 bf16) -> conflict-free ldmatrix
#define DPB 48                    // diffB row pitch bytes (16 bf16 + pad) -> conflict-free
#define W1PB 272                  // W1B row pitch bytes

// ---------------- smem layout (bytes) ----------------
#define OFF_W2HI 0                // 128 x 136 bf16 = 34816
#define OFF_W2LO 34816
#define OFF_HHI  69632            // h hi (128 tok x 136 bf16)
#define OFF_HLO  104448           // h lo           (ends 139264)
#define OFF_DBHI 139264           // diff hi 128 x 48B = 6144
#define OFF_DBLO 145408           // diff lo        (ends 151552)
#define OFF_W1HI 151552           // W1 hi 16 x 272B = 4352
#define OFF_W1LO 155904           // W1 lo          (ends 160256)
#define OFF_MS   160256           // 128 f32
#define OFF_B2   160768
#define OFF_AS   161280
#define OFF_CS   161792
#define SMEM_MAIN 162304
#define OFF_STAGE OFF_HHI         // stage overlays h after GEMM2 (67584 <= 69632)
#define STG_W 132                 // stage row stride (floats)

__device__ __forceinline__ uint32_t smem_u32(const void* p) {
    uint32_t a;
    asm("{ .reg .u64 t; cvta.to.shared.u64 t, %1; cvt.u32.u64 %0, t; }" : "=r"(a) : "l"(p));
    return a;
}
__device__ __forceinline__ void ldm_x4(uint32_t* r, uint32_t addr) {
    asm volatile("ldmatrix.sync.aligned.m8n8.x4.shared.b16 {%0,%1,%2,%3}, [%4];"
                 : "=r"(r[0]), "=r"(r[1]), "=r"(r[2]), "=r"(r[3]) : "r"(addr));
}
__device__ __forceinline__ void ldm_x4_t(uint32_t* r, uint32_t addr) {
    asm volatile("ldmatrix.sync.aligned.m8n8.x4.trans.shared.b16 {%0,%1,%2,%3}, [%4];"
                 : "=r"(r[0]), "=r"(r[1]), "=r"(r[2]), "=r"(r[3]) : "r"(addr));
}
__device__ __forceinline__ void mma_bf16(float* d, const uint32_t* a, uint32_t b0, uint32_t b1) {
    asm volatile("mma.sync.aligned.m16n8k16.row.col.f32.bf16.bf16.f32 "
                 "{%0,%1,%2,%3}, {%4,%5,%6,%7}, {%8,%9}, {%0,%1,%2,%3};"
                 : "+f"(d[0]), "+f"(d[1]), "+f"(d[2]), "+f"(d[3])
                 : "r"(a[0]), "r"(a[1]), "r"(a[2]), "r"(a[3]), "r"(b0), "r"(b1));
}
__device__ __forceinline__ uint32_t pack_hi(float x0, float x1, float& r0, float& r1) {
    __nv_bfloat16 h0 = __float2bfloat16(x0), h1 = __float2bfloat16(x1);
    r0 = x0 - __bfloat162float(h0); r1 = x1 - __bfloat162float(h1);
    return ((uint32_t)__bfloat16_as_ushort(h1) << 16) | __bfloat16_as_ushort(h0);
}
__device__ __forceinline__ uint32_t pack_bf(float x0, float x1) {
    __nv_bfloat16 h0 = __float2bfloat16(x0), h1 = __float2bfloat16(x1);
    return ((uint32_t)__bfloat16_as_ushort(h1) << 16) | __bfloat16_as_ushort(h0);
}

// ---------------- global scratch ----------------
#define NSTAT 136                      // su[15] + S_upper[120] + cnt
#define STAT_BLOCKS 512
__device__ float g_p2[STAT_BLOCKS * NSTAT];
__device__ float g_A[DD];
__device__ float g_C[DD];

// ===== Pass A: masked 2nd-moment matrix; 2 thread-groups split the triangle =====
// group0 (threads 0-127):  su[15] + S rows 0-4 (65 entries) + cnt   -> slots 0..79, 135
// group1 (threads 128-255): S rows 5-14 (55 entries)                -> slots 80..134
__global__ void __launch_bounds__(256) k_stats2(const float* __restrict__ diff,
                                                const int* __restrict__ mask) {
    __shared__ float ds[512 * CIN];
    __shared__ float msk[512];
    __shared__ float red[4 * 81 + 4 * 55];
    int tid = threadIdx.x, lid = tid & 31, w = tid >> 5;
    int tok0 = blockIdx.x * 512;

    for (int i = tid; i < 512 * CIN; i += 256) ds[i] = diff[(size_t)tok0 * CIN + i];
    for (int i = tid; i < 512; i += 256) msk[i] = mask[tok0 + i] ? 1.0f : 0.0f;
    __syncthreads();

    int gt = tid & 127;
    if (tid < 128) {
        float su[CIN], S0[65], cnt = 0.f;
        #pragma unroll
        for (int i = 0; i < CIN; i++) su[i] = 0.f;
        #pragma unroll
        for (int i = 0; i < 65; i++) S0[i] = 0.f;
        for (int r = 0; r < 4; r++) {
            int t = r * 128 + gt;
            if (msk[t] != 0.f) {
                float v[CIN];
                #pragma unroll
                for (int c = 0; c < CIN; c++) v[c] = ds[t * CIN + c];
                cnt += 1.f;
                #pragma unroll
                for (int i = 0; i < CIN; i++) su[i] += v[i];
                int idx = 0;
                #pragma unroll
                for (int i = 0; i < 5; i++)
                    #pragma unroll
                    for (int j = i; j < CIN; j++) { S0[idx] += v[i] * v[j]; idx++; }
            }
        }
        #pragma unroll
        for (int o = 16; o; o >>= 1) {
            #pragma unroll
            for (int i = 0; i < CIN; i++) su[i] += __shfl_down_sync(0xffffffffu, su[i], o);
            #pragma unroll
            for (int i = 0; i < 65; i++) S0[i] += __shfl_down_sync(0xffffffffu, S0[i], o);
            cnt += __shfl_down_sync(0xffffffffu, cnt, o);
        }
        if (lid == 0) {
            #pragma unroll
            for (int i = 0; i < CIN; i++) red[w * 81 + i] = su[i];
            #pragma unroll
            for (int i = 0; i < 65; i++) red[w * 81 + 15 + i] = S0[i];
            red[w * 81 + 80] = cnt;
        }
    } else {
        float S1[55];
        #pragma unroll
        for (int i = 0; i < 55; i++) S1[i] = 0.f;
        for (int r = 0; r < 4; r++) {
            int t = r * 128 + gt;
            if (msk[t] != 0.f) {
                float v[CIN];
                #pragma unroll
                for (int c = 0; c < CIN; c++) v[c] = ds[t * CIN + c];
                int idx = 0;
                #pragma unroll
                for (int i = 5; i < CIN; i++)
                    #pragma unroll
                    for (int j = i; j < CIN; j++) { S1[idx] += v[i] * v[j]; idx++; }
            }
        }
        #pragma unroll
        for (int o = 16; o; o >>= 1)
            #pragma unroll
            for (int i = 0; i < 55; i++) S1[i] += __shfl_down_sync(0xffffffffu, S1[i], o);
        if (lid == 0) {
            #pragma unroll
            for (int i = 0; i < 55; i++) red[324 + (w - 4) * 55 + i] = S1[i];
        }
    }
    __syncthreads();
    if (tid < NSTAT) {
        float s = 0.f;
        if (tid < 80) {          // su (0-14) + S rows 0-4 (15-79): group0 slot tid
            #pragma unroll
            for (int ww = 0; ww < 4; ww++) s += red[ww * 81 + tid];
        } else if (tid < 135) {  // S rows 5-14: group1 slot tid-80
            #pragma unroll
            for (int ww = 0; ww < 4; ww++) s += red[324 + ww * 55 + (tid - 80)];
        } else {                 // cnt
            #pragma unroll
            for (int ww = 0; ww < 4; ww++) s += red[ww * 81 + 80];
        }
        g_p2[blockIdx.x * NSTAT + tid] = s;
    }
}

// ================= Pass B: finalize BN affine (parallel 4-way reduction) =================
__global__ void __launch_bounds__(544) k_final2(const float* __restrict__ W1,
                                                const float* __restrict__ b1,
                                                const float* __restrict__ gamma,
                                                const float* __restrict__ beta) {
    __shared__ float part[4 * NSTAT];
    __shared__ float tot[NSTAT];
    __shared__ float Sf[CIN][CIN];
    __shared__ float suS[CIN];
    __shared__ float cntS;
    int tid = threadIdx.x;
    {
        int grp = tid / NSTAT, j = tid - grp * NSTAT;   // 4 groups x 136
        float s = 0.f;
        for (int b = grp; b < STAT_BLOCKS; b += 4) s += g_p2[b * NSTAT + j];
        part[grp * NSTAT + j] = s;
    }
    __syncthreads();
    if (tid < NSTAT)
        tot[tid] = part[tid] + part[NSTAT + tid] + part[2 * NSTAT + tid] + part[3 * NSTAT + tid];
    __syncthreads();
    if (tid < CIN * CIN) {
        int i = tid / CIN, j = tid % CIN;
        int a = i < j ? i : j, b = i < j ? j : i;
        Sf[i][j] = tot[CIN + a * CIN - (a * (a - 1)) / 2 + (b - a)];
    }
    if (tid < CIN) suS[tid] = tot[tid];
    if (tid == 0) cntS = tot[135];
    __syncthreads();
    if (tid < DD) {
        int d = tid;
        float w[CIN];
        #pragma unroll
        for (int c = 0; c < CIN; c++) w[c] = W1[c * DD + d];
        float sh = 0.f;
        #pragma unroll
        for (int c = 0; c < CIN; c++) sh += suS[c] * w[c];
        float q = 0.f;
        #pragma unroll
        for (int i = 0; i < CIN; i++) {
            float acc = 0.f;
            #pragma unroll
            for (int j = 0; j < CIN; j++) acc += Sf[i][j] * w[j];
            q += w[i] * acc;
        }
        float cnt = fmaxf(cntS, 1.f);
        float bb = b1[d];
        float mean = (sh + cnt * bb) / cnt;
        float sum2 = q + 2.f * bb * sh + cnt * bb * bb;
        float var = fmaxf(sum2 / cnt - mean * mean, 0.f);
        float A = gamma[d] * rsqrtf(var + 1e-5f);
        g_A[d] = A;
        g_C[d] = beta[d] + (bb - mean) * A;
    }
}

// ========== Pass C (persistent): HMMA GEMM1 + HMMA GEMM2, both split-bf16 ==========
__global__ void __launch_bounds__(256, 1) k_main(
        const float* __restrict__ diff, const int* __restrict__ mask,
        const float* __restrict__ W1, const float* __restrict__ W2,
        const float* __restrict__ b2, float* __restrict__ out, int do_tail) {
    extern __shared__ char sm[];
    float* smf = (float*)sm;
    uint32_t smb = smem_u32(sm);
    int tid = threadIdx.x, lid = tid & 31, wid = tid >> 5;

    // --- once per CTA: split W2 (for GEMM2 B) and W1 (for GEMM1 B, K padded to 16) ---
    for (int idx = tid; idx < DD * DD; idx += 256) {
        int d = idx >> 7, e = idx & 127;
        float v = W2[idx];
        float lo0, lo1; (void)lo1;
        __nv_bfloat16 vh = __float2bfloat16(v);
        lo0 = v - __bfloat162float(vh);
        *(__nv_bfloat16*)(sm + OFF_W2HI + d * PBB + e * 2) = vh;
        *(__nv_bfloat16*)(sm + OFF_W2LO + d * PBB + e * 2) = __float2bfloat16(lo0);
    }
    for (int idx = tid; idx < 16 * DD; idx += 256) {
        int k = idx >> 7, n = idx & 127;
        float v = (k < CIN) ? W1[k * DD + n] : 0.f;
        __nv_bfloat16 vh = __float2bfloat16(v);
        float lo = v - __bfloat162float(vh);
        *(__nv_bfloat16*)(sm + OFF_W1HI + k * W1PB + n * 2) = vh;
        *(__nv_bfloat16*)(sm + OFF_W1LO + k * W1PB + n * 2) = __float2bfloat16(lo);
    }
    if (tid < DD) {
        smf[OFF_B2/4 + tid] = b2[tid];
        smf[OFF_AS/4 + tid] = g_A[tid];
        smf[OFF_CS/4 + tid] = g_C[tid];
    }

    // warp tile geometry: 32 tokens x 64 channels per warp (both GEMMs)
    int wt = wid >> 1;                 // 0..3 token quarter
    int c0 = (wid & 1) * 64;           // channel half base
    int t0w = wt * 32;
    int g = lid >> 3, i8 = lid & 7;
    // GEMM2 operand bases
    uint32_t aHi0 = smb + OFF_HHI + (uint32_t)(t0w + i8 + ((g & 1) << 3)) * PBB + ((g >> 1) << 4);
    uint32_t aHi1 = aHi0 + 16 * PBB;
    uint32_t bBase = smb + OFF_W2HI + (uint32_t)(i8 + ((g & 1) << 3)) * PBB
                   + ((uint32_t)c0 << 1) + ((g >> 1) << 4);
    const uint32_t LO_A = OFF_HLO - OFF_HHI;
    const uint32_t LO_B = OFF_W2LO - OFF_W2HI;
    // GEMM1 operand bases
    uint32_t aD0 = smb + OFF_DBHI + (uint32_t)(t0w + i8 + ((g & 1) << 3)) * DPB + ((g >> 1) << 4);
    uint32_t wB  = smb + OFF_W1HI + (uint32_t)(i8 + ((g & 1) << 3)) * W1PB
                 + ((uint32_t)c0 << 1) + ((g >> 1) << 4);
    const uint32_t LO_D  = OFF_DBLO - OFF_DBHI;
    const uint32_t LO_W1 = OFF_W1LO - OFF_W1HI;

    // --- persistent loop over token tiles ---
    for (int tile = blockIdx.x; tile < NTILES; tile += gridDim.x) {
        int tok0 = tile * DD;
        // stage diff tile as split bf16 (K padded to 16); also mask
        for (int idx = tid; idx < DD * 16; idx += 256) {
            int t = idx >> 4, c = idx & 15;
            float v = (c < CIN) ? diff[(size_t)(tok0 + t) * CIN + c] : 0.f;
            __nv_bfloat16 vh = __float2bfloat16(v);
            float lo = v - __bfloat162float(vh);
            *(__nv_bfloat16*)(sm + OFF_DBHI + t * DPB + c * 2) = vh;
            *(__nv_bfloat16*)(sm + OFF_DBLO + t * DPB + c * 2) = __float2bfloat16(lo);
        }
        if (tid < DD) smf[OFF_MS/4 + tid] = mask[tok0 + tid] ? 1.0f : 0.0f;
        __syncthreads();   // diffB ready; also: all threads past prev-tile stage reads

        // ---- GEMM1 (HMMA split-bf16): h = diff @ W1, then BN+ReLU+split -> h smem ----
        {
            float acc1[2][8][4];
            #pragma unroll
            for (int mt = 0; mt < 2; mt++)
                #pragma unroll
                for (int n = 0; n < 8; n++)
                    #pragma unroll
                    for (int j = 0; j < 4; j++) acc1[mt][n][j] = 0.f;

            uint32_t adh[2][4], adl[2][4];
            ldm_x4(adh[0], aD0);
            ldm_x4(adl[0], aD0 + LO_D);
            ldm_x4(adh[1], aD0 + 16 * DPB);
            ldm_x4(adl[1], aD0 + 16 * DPB + LO_D);
            #pragma unroll
            for (int nb2 = 0; nb2 < 4; nb2++) {
                uint32_t wbh[4], wbl[4];
                ldm_x4_t(wbh, wB + nb2 * 32);
                ldm_x4_t(wbl, wB + LO_W1 + nb2 * 32);
                int n0 = nb2 * 2;
                #pragma unroll
                for (int mt = 0; mt < 2; mt++) {
                    mma_bf16(acc1[mt][n0],     adh[mt], wbh[0], wbh[1]);
                    mma_bf16(acc1[mt][n0],     adl[mt], wbh[0], wbh[1]);
                    mma_bf16(acc1[mt][n0],     adh[mt], wbl[0], wbl[1]);
                    mma_bf16(acc1[mt][n0 + 1], adh[mt], wbh[2], wbh[3]);
                    mma_bf16(acc1[mt][n0 + 1], adl[mt], wbh[2], wbh[3]);
                    mma_bf16(acc1[mt][n0 + 1], adh[mt], wbl[2], wbl[3]);
                }
            }
            // fragment epilogue: BN + ReLU + split -> h hi/lo
            #pragma unroll
            for (int nb = 0; nb < 8; nb++) {
                int col = c0 + nb * 8 + (lid & 3) * 2;
                float A0 = smf[OFF_AS/4 + col], A1 = smf[OFF_AS/4 + col + 1];
                float C0 = smf[OFF_CS/4 + col], C1 = smf[OFF_CS/4 + col + 1];
                #pragma unroll
                for (int mt = 0; mt < 2; mt++) {
                    int row = t0w + mt * 16 + (lid >> 2);
                    float x0 = fmaxf(acc1[mt][nb][0] * A0 + C0, 0.f);
                    float x1 = fmaxf(acc1[mt][nb][1] * A1 + C1, 0.f);
                    float x2 = fmaxf(acc1[mt][nb][2] * A0 + C0, 0.f);
                    float x3 = fmaxf(acc1[mt][nb][3] * A1 + C1, 0.f);
                    float l0, l1, l2, l3;
                    uint32_t hiA = pack_hi(x0, x1, l0, l1);
                    uint32_t hiB = pack_hi(x2, x3, l2, l3);
                    *(uint32_t*)(sm + OFF_HHI + row * PBB + col * 2)       = hiA;
                    *(uint32_t*)(sm + OFF_HLO + row * PBB + col * 2)       = pack_bf(l0, l1);
                    *(uint32_t*)(sm + OFF_HHI + (row + 8) * PBB + col * 2) = hiB;
                    *(uint32_t*)(sm + OFF_HLO + (row + 8) * PBB + col * 2) = pack_bf(l2, l3);
                }
            }
        }
        __syncthreads();

        // ---- GEMM2 (HMMA split-bf16): out = h @ W2 ----
        float acc[2][8][4];
        #pragma unroll
        for (int mt = 0; mt < 2; mt++)
            #pragma unroll
            for (int n = 0; n < 8; n++)
                #pragma unroll
                for (int j = 0; j < 4; j++) acc[mt][n][j] = 0.f;

        #pragma unroll 2
        for (int kk = 0; kk < 8; kk++) {
            uint32_t ah[2][4], al[2][4];
            ldm_x4(ah[0], aHi0 + kk * 32);
            ldm_x4(al[0], aHi0 + LO_A + kk * 32);
            ldm_x4(ah[1], aHi1 + kk * 32);
            ldm_x4(al[1], aHi1 + LO_A + kk * 32);
            uint32_t bkoff = (uint32_t)kk * 16 * PBB;
            #pragma unroll
            for (int nb2 = 0; nb2 < 4; nb2++) {
                uint32_t bh[4], bl[4];
                ldm_x4_t(bh, bBase + bkoff + nb2 * 32);
                ldm_x4_t(bl, bBase + LO_B + bkoff + nb2 * 32);
                int n0 = nb2 * 2;
                #pragma unroll
                for (int mt = 0; mt < 2; mt++) {
                    mma_bf16(acc[mt][n0],     ah[mt], bh[0], bh[1]);
                    mma_bf16(acc[mt][n0],     al[mt], bh[0], bh[1]);
                    mma_bf16(acc[mt][n0],     ah[mt], bl[0], bl[1]);
                    mma_bf16(acc[mt][n0 + 1], ah[mt], bh[2], bh[3]);
                    mma_bf16(acc[mt][n0 + 1], al[mt], bh[2], bh[3]);
                    mma_bf16(acc[mt][n0 + 1], ah[mt], bl[2], bl[3]);
                }
            }
        }
        __syncthreads();   // h reads done -> safe to overlay stage

        // epilogue: bias + mask -> stage smem
        #pragma unroll
        for (int mt = 0; mt < 2; mt++) {
            int row = t0w + mt * 16 + (lid >> 2);
            float m1 = smf[OFF_MS/4 + row];
            float m2 = smf[OFF_MS/4 + row + 8];
            #pragma unroll
            for (int nt = 0; nt < 8; nt++) {
                int col = c0 + nt * 8 + (lid & 3) * 2;
                float b0 = smf[OFF_B2/4 + col], b1v = smf[OFF_B2/4 + col + 1];
                smf[OFF_STAGE/4 + row * STG_W + col]           = (acc[mt][nt][0] + b0)  * m1;
                smf[OFF_STAGE/4 + row * STG_W + col + 1]       = (acc[mt][nt][1] + b1v) * m1;
                smf[OFF_STAGE/4 + (row + 8) * STG_W + col]     = (acc[mt][nt][2] + b0)  * m2;
                smf[OFF_STAGE/4 + (row + 8) * STG_W + col + 1] = (acc[mt][nt][3] + b1v) * m2;
            }
        }
        __syncthreads();

        // coalesced float4 stores (+ fused mask-tail echo)
        #pragma unroll
        for (int i = 0; i < 16; i++) {
            int idx = tid + i * 256;
            int token = idx >> 5, c4 = idx & 31;
            float4 v = *(const float4*)&smf[OFF_STAGE/4 + token * STG_W + c4 * 4];
            *(float4*)&out[(size_t)(tok0 + token) * DD + c4 * 4] = v;
        }
        if (do_tail && tid < DD)
            out[(size_t)TOKENS * DD + tok0 + tid] = smf[OFF_MS/4 + tid];
    }
}

extern "C" void kernel_launch(void* const* d_in, const int* in_sizes, int n_in,
                              void* d_out, int out_size) {
    const float* diff  = (const float*)d_in[0];
    const int*   mask  = (const int*)d_in[1];
    const float* W1    = (const float*)d_in[2];
    const float* b1    = (const float*)d_in[3];
    const float* gamma = (const float*)d_in[4];
    const float* beta  = (const float*)d_in[5];
    const float* W2    = (const float*)d_in[6];
    const float* b2    = (const float*)d_in[7];
    float* out = (float*)d_out;
    int do_tail = (out_size > TOKENS * DD) ? 1 : 0;

    cudaFuncSetAttribute(k_main, cudaFuncAttributeMaxDynamicSharedMemorySize, SMEM_MAIN);

    k_stats2<<<STAT_BLOCKS, 256>>>(diff, mask);
    k_final2<<<1, 544>>>(W1, b1, gamma, beta);
    k_main<<<148, 256, SMEM_MAIN>>>(diff, mask, W1, W2, b2, out, do_tail);
}

// round 15
// speedup vs baseline: 4.2751x; 1.1683x over previous
#include <cuda_runtime.h>
#include <cuda_bf16.h>
#include <cstdint>

// ---------------- problem constants ----------------
#define TOKENS (8*128*256)        // 262144
#define CIN 15
#define DD 128
#define NTILES (TOKENS/DD)        // 2048 token tiles
#define PBB 272                   // h / W2 row pitch bytes (136 bf16) -> conflict-free ldmatrix
#define DPB 48                    // diffB row pitch bytes (16 bf16 + pad) -> conflict-free
#define W1PB 272                  // W1B row pitch bytes

// ---------------- k_main smem layout (bytes) ----------------
#define OFF_W2HI 0                // 128 x 136 bf16 = 34816
#define OFF_W2LO 34816
#define OFF_HHI  69632            // h hi (128 tok x 136 bf16)
#define OFF_HLO  104448           // h lo           (ends 139264)
#define OFF_DBHI 139264           // diff hi 128 x 48B = 6144
#define OFF_DBLO 145408           // diff lo        (ends 151552)
#define OFF_W1HI 151552           // W1 hi 16 x 272B = 4352
#define OFF_W1LO 155904           // W1 lo          (ends 160256)
#define OFF_MS   160256           // 128 f32
#define OFF_B2   160768
#define OFF_AS   161280
#define OFF_CS   161792
#define SMEM_MAIN 162304

// ---------------- k_stats smem layout (bytes) ----------------
#define SOFF_DS   0               // 512*15 f32 = 30720
#define SOFF_MSK  30720           // 512 f32
#define SOFF_UHI  32768           // 16 x 1040B (pitch 520 bf16)
#define SOFF_ULO  49408
#define SOFF_RED  66048           // 8 warps x 256 f32 = 8192
#define SMEM_STAT 74240
#define UPITCH 1040

__device__ __forceinline__ uint32_t smem_u32(const void* p) {
    uint32_t a;
    asm("{ .reg .u64 t; cvta.to.shared.u64 t, %1; cvt.u32.u64 %0, t; }" : "=r"(a) : "l"(p));
    return a;
}
__device__ __forceinline__ void ldm_x4(uint32_t* r, uint32_t addr) {
    asm volatile("ldmatrix.sync.aligned.m8n8.x4.shared.b16 {%0,%1,%2,%3}, [%4];"
                 : "=r"(r[0]), "=r"(r[1]), "=r"(r[2]), "=r"(r[3]) : "r"(addr));
}
__device__ __forceinline__ void ldm_x4_t(uint32_t* r, uint32_t addr) {
    asm volatile("ldmatrix.sync.aligned.m8n8.x4.trans.shared.b16 {%0,%1,%2,%3}, [%4];"
                 : "=r"(r[0]), "=r"(r[1]), "=r"(r[2]), "=r"(r[3]) : "r"(addr));
}
__device__ __forceinline__ void mma_bf16(float* d, const uint32_t* a, uint32_t b0, uint32_t b1) {
    asm volatile("mma.sync.aligned.m16n8k16.row.col.f32.bf16.bf16.f32 "
                 "{%0,%1,%2,%3}, {%4,%5,%6,%7}, {%8,%9}, {%0,%1,%2,%3};"
                 : "+f"(d[0]), "+f"(d[1]), "+f"(d[2]), "+f"(d[3])
                 : "r"(a[0]), "r"(a[1]), "r"(a[2]), "r"(a[3]), "r"(b0), "r"(b1));
}
__device__ __forceinline__ uint32_t pack_hi(float x0, float x1, float& r0, float& r1) {
    __nv_bfloat16 h0 = __float2bfloat16(x0), h1 = __float2bfloat16(x1);
    r0 = x0 - __bfloat162float(h0); r1 = x1 - __bfloat162float(h1);
    return ((uint32_t)__bfloat16_as_ushort(h1) << 16) | __bfloat16_as_ushort(h0);
}
__device__ __forceinline__ uint32_t pack_bf(float x0, float x1) {
    __nv_bfloat16 h0 = __float2bfloat16(x0), h1 = __float2bfloat16(x1);
    return ((uint32_t)__bfloat16_as_ushort(h1) << 16) | __bfloat16_as_ushort(h0);
}

// ---------------- global scratch ----------------
#define NSTAT 136                      // su[15] + S_upper[120] + cnt
#define STAT_BLOCKS 512
__device__ float g_p2[STAT_BLOCKS * NSTAT];
__device__ float g_A[DD];
__device__ float g_C[DD];

// ===== Pass A: masked 2nd-moment matrix S = (mU)^T(mU) via split-bf16 HMMA =====
// U[t] = (diff[t]*m, m). S[i][15]=su_i, S[15][15]=cnt, S upper = moments.
// U stored [feat][token] => B fragment comes from NON-trans ldmatrix (rows=feat),
// and the SAME ldm_x4 registers serve as both A and B fragments:
//   A = {r0,r1,r2,r3};  B n-block0 = (r0, r2);  B n-block1 = (r1, r3).
__global__ void __launch_bounds__(256) k_stats2(const float* __restrict__ diff,
                                                const int* __restrict__ mask) {
    extern __shared__ char ssm[];
    float* ds  = (float*)(ssm + SOFF_DS);
    float* msk = (float*)(ssm + SOFF_MSK);
    float* red = (float*)(ssm + SOFF_RED);
    uint32_t smb = smem_u32(ssm);
    int tid = threadIdx.x, lid = tid & 31, w = tid >> 5;
    int tok0 = blockIdx.x * 512;

    for (int i = tid; i < 512 * CIN; i += 256) ds[i] = diff[(size_t)tok0 * CIN + i];
    for (int i = tid; i < 512; i += 256) msk[i] = mask[tok0 + i] ? 1.0f : 0.0f;
    __syncthreads();

    // transpose + mask + split to bf16 hi/lo: U[16 feat][512 tok]
    for (int idx = tid; idx < 16 * 512; idx += 256) {
        int c = idx >> 9, t = idx & 511;
        float m = msk[t];
        float v = (c < CIN) ? ds[t * CIN + c] * m : m;
        __nv_bfloat16 vh = __float2bfloat16(v);
        float lo = v - __bfloat162float(vh);
        *(__nv_bfloat16*)(ssm + SOFF_UHI + c * UPITCH + t * 2) = vh;
        *(__nv_bfloat16*)(ssm + SOFF_ULO + c * UPITCH + t * 2) = __float2bfloat16(lo);
    }
    __syncthreads();

    // warp w: tokens [w*64, w*64+64), 4 chunks of 16
    float accD[2][4] = {{0.f,0.f,0.f,0.f},{0.f,0.f,0.f,0.f}};
    {
        int g = lid >> 3, i8 = lid & 7;
        uint32_t frag = (uint32_t)(i8 + ((g & 1) << 3)) * UPITCH + ((g >> 1) << 4);
        #pragma unroll
        for (int ch = 0; ch < 4; ch++) {
            uint32_t toff = (uint32_t)(w * 64 + ch * 16) * 2;
            uint32_t uh[4], ul[4];
            ldm_x4(uh, smb + SOFF_UHI + frag + toff);
            ldm_x4(ul, smb + SOFF_ULO + frag + toff);
            // n-block 0 (feat j 0-7): b0=uh[0] (k0-7), b1=uh[2] (k8-15)
            mma_bf16(accD[0], uh, uh[0], uh[2]);
            mma_bf16(accD[0], ul, uh[0], uh[2]);
            mma_bf16(accD[0], uh, ul[0], ul[2]);
            // n-block 1 (feat j 8-15): b0=uh[1], b1=uh[3]
            mma_bf16(accD[1], uh, uh[1], uh[3]);
            mma_bf16(accD[1], ul, uh[1], uh[3]);
            mma_bf16(accD[1], uh, ul[1], ul[3]);
        }
    }
    // store fragments: red[w][i][j]; D[i][j]: i = lid>>2 (+8), j = n*8 + (lid&3)*2 (+1)
    {
        int i = lid >> 2, jq = (lid & 3) * 2;
        #pragma unroll
        for (int n = 0; n < 2; n++) {
            int j = n * 8 + jq;
            red[w * 256 + i * 16 + j]           = accD[n][0];
            red[w * 256 + i * 16 + j + 1]       = accD[n][1];
            red[w * 256 + (i + 8) * 16 + j]     = accD[n][2];
            red[w * 256 + (i + 8) * 16 + j + 1] = accD[n][3];
        }
    }
    __syncthreads();
    // cross-warp reduce + scatter to NSTAT layout
    {
        int i = tid >> 4, j = tid & 15;
        int slot = -1;
        if (i == 15 && j == 15) slot = 135;                       // cnt
        else if (j == 15 && i < 15) slot = i;                     // su_i
        else if (i <= j && j < 15) slot = 15 + i * 15 - (i * (i - 1)) / 2 + (j - i);
        if (slot >= 0) {
            float s = 0.f;
            #pragma unroll
            for (int ww = 0; ww < 8; ww++) s += red[ww * 256 + i * 16 + j];
            g_p2[blockIdx.x * NSTAT + slot] = s;
        }
    }
}

// ================= Pass B: finalize BN affine (parallel 4-way reduction) =================
__global__ void __launch_bounds__(544) k_final2(const float* __restrict__ W1,
                                                const float* __restrict__ b1,
                                                const float* __restrict__ gamma,
                                                const float* __restrict__ beta) {
    __shared__ float part[4 * NSTAT];
    __shared__ float tot[NSTAT];
    __shared__ float Sf[CIN][CIN];
    __shared__ float suS[CIN];
    __shared__ float cntS;
    int tid = threadIdx.x;
    {
        int grp = tid / NSTAT, j = tid - grp * NSTAT;   // 4 groups x 136
        float s = 0.f;
        for (int b = grp; b < STAT_BLOCKS; b += 4) s += g_p2[b * NSTAT + j];
        part[grp * NSTAT + j] = s;
    }
    __syncthreads();
    if (tid < NSTAT)
        tot[tid] = part[tid] + part[NSTAT + tid] + part[2 * NSTAT + tid] + part[3 * NSTAT + tid];
    __syncthreads();
    if (tid < CIN * CIN) {
        int i = tid / CIN, j = tid % CIN;
        int a = i < j ? i : j, b = i < j ? j : i;
        Sf[i][j] = tot[CIN + a * CIN - (a * (a - 1)) / 2 + (b - a)];
    }
    if (tid < CIN) suS[tid] = tot[tid];
    if (tid == 0) cntS = tot[135];
    __syncthreads();
    if (tid < DD) {
        int d = tid;
        float w[CIN];
        #pragma unroll
        for (int c = 0; c < CIN; c++) w[c] = W1[c * DD + d];
        float sh = 0.f;
        #pragma unroll
        for (int c = 0; c < CIN; c++) sh += suS[c] * w[c];
        float q = 0.f;
        #pragma unroll
        for (int i = 0; i < CIN; i++) {
            float acc = 0.f;
            #pragma unroll
            for (int j = 0; j < CIN; j++) acc += Sf[i][j] * w[j];
            q += w[i] * acc;
        }
        float cnt = fmaxf(cntS, 1.f);
        float bb = b1[d];
        float mean = (sh + cnt * bb) / cnt;
        float sum2 = q + 2.f * bb * sh + cnt * bb * bb;
        float var = fmaxf(sum2 / cnt - mean * mean, 0.f);
        float A = gamma[d] * rsqrtf(var + 1e-5f);
        g_A[d] = A;
        g_C[d] = beta[d] + (bb - mean) * A;
    }
}

// ========== Pass C (persistent): HMMA GEMM1 + HMMA GEMM2, direct-STG epilogue ==========
__global__ void __launch_bounds__(256, 1) k_main(
        const float* __restrict__ diff, const int* __restrict__ mask,
        const float* __restrict__ W1, const float* __restrict__ W2,
        const float* __restrict__ b2, float* __restrict__ out, int do_tail) {
    extern __shared__ char sm[];
    float* smf = (float*)sm;
    uint32_t smb = smem_u32(sm);
    int tid = threadIdx.x, lid = tid & 31, wid = tid >> 5;

    // --- once per CTA: split W2 (GEMM2 B) and W1 (GEMM1 B, K padded to 16) ---
    for (int idx = tid; idx < DD * DD; idx += 256) {
        int d = idx >> 7, e = idx & 127;
        float v = W2[idx];
        __nv_bfloat16 vh = __float2bfloat16(v);
        float lo = v - __bfloat162float(vh);
        *(__nv_bfloat16*)(sm + OFF_W2HI + d * PBB + e * 2) = vh;
        *(__nv_bfloat16*)(sm + OFF_W2LO + d * PBB + e * 2) = __float2bfloat16(lo);
    }
    for (int idx = tid; idx < 16 * DD; idx += 256) {
        int k = idx >> 7, n = idx & 127;
        float v = (k < CIN) ? W1[k * DD + n] : 0.f;
        __nv_bfloat16 vh = __float2bfloat16(v);
        float lo = v - __bfloat162float(vh);
        *(__nv_bfloat16*)(sm + OFF_W1HI + k * W1PB + n * 2) = vh;
        *(__nv_bfloat16*)(sm + OFF_W1LO + k * W1PB + n * 2) = __float2bfloat16(lo);
    }
    if (tid < DD) {
        smf[OFF_B2/4 + tid] = b2[tid];
        smf[OFF_AS/4 + tid] = g_A[tid];
        smf[OFF_CS/4 + tid] = g_C[tid];
    }

    // warp tile: 32 tokens x 64 channels (both GEMMs)
    int wt = wid >> 1;
    int c0 = (wid & 1) * 64;
    int t0w = wt * 32;
    int g = lid >> 3, i8 = lid & 7;
    uint32_t aHi0 = smb + OFF_HHI + (uint32_t)(t0w + i8 + ((g & 1) << 3)) * PBB + ((g >> 1) << 4);
    uint32_t aHi1 = aHi0 + 16 * PBB;
    uint32_t bBase = smb + OFF_W2HI + (uint32_t)(i8 + ((g & 1) << 3)) * PBB
                   + ((uint32_t)c0 << 1) + ((g >> 1) << 4);
    const uint32_t LO_A = OFF_HLO - OFF_HHI;
    const uint32_t LO_B = OFF_W2LO - OFF_W2HI;
    uint32_t aD0 = smb + OFF_DBHI + (uint32_t)(t0w + i8 + ((g & 1) << 3)) * DPB + ((g >> 1) << 4);
    uint32_t wB  = smb + OFF_W1HI + (uint32_t)(i8 + ((g & 1) << 3)) * W1PB
                 + ((uint32_t)c0 << 1) + ((g >> 1) << 4);
    const uint32_t LO_D  = OFF_DBLO - OFF_DBHI;
    const uint32_t LO_W1 = OFF_W1LO - OFF_W1HI;

    for (int tile = blockIdx.x; tile < NTILES; tile += gridDim.x) {
        int tok0 = tile * DD;
        __syncthreads();   // (a) protect MS/diffB against prev-iter epilogue readers

        // stage diff tile as split bf16 (K padded to 16); mask
        for (int idx = tid; idx < DD * 16; idx += 256) {
            int t = idx >> 4, c = idx & 15;
            float v = (c < CIN) ? diff[(size_t)(tok0 + t) * CIN + c] : 0.f;
            __nv_bfloat16 vh = __float2bfloat16(v);
            float lo = v - __bfloat162float(vh);
            *(__nv_bfloat16*)(sm + OFF_DBHI + t * DPB + c * 2) = vh;
            *(__nv_bfloat16*)(sm + OFF_DBLO + t * DPB + c * 2) = __float2bfloat16(lo);
        }
        if (tid < DD) smf[OFF_MS/4 + tid] = mask[tok0 + tid] ? 1.0f : 0.0f;
        __syncthreads();   // (b) diffB/MS ready

        // ---- GEMM1: h = diff @ W1 (split-bf16 HMMA), BN+ReLU+split -> h smem ----
        {
            float acc1[2][8][4];
            #pragma unroll
            for (int mt = 0; mt < 2; mt++)
                #pragma unroll
                for (int n = 0; n < 8; n++)
                    #pragma unroll
                    for (int j = 0; j < 4; j++) acc1[mt][n][j] = 0.f;

            uint32_t adh[2][4], adl[2][4];
            ldm_x4(adh[0], aD0);
            ldm_x4(adl[0], aD0 + LO_D);
            ldm_x4(adh[1], aD0 + 16 * DPB);
            ldm_x4(adl[1], aD0 + 16 * DPB + LO_D);
            #pragma unroll
            for (int nb2 = 0; nb2 < 4; nb2++) {
                uint32_t wbh[4], wbl[4];
                ldm_x4_t(wbh, wB + nb2 * 32);
                ldm_x4_t(wbl, wB + LO_W1 + nb2 * 32);
                int n0 = nb2 * 2;
                #pragma unroll
                for (int mt = 0; mt < 2; mt++) {
                    mma_bf16(acc1[mt][n0],     adh[mt], wbh[0], wbh[1]);
                    mma_bf16(acc1[mt][n0],     adl[mt], wbh[0], wbh[1]);
                    mma_bf16(acc1[mt][n0],     adh[mt], wbl[0], wbl[1]);
                    mma_bf16(acc1[mt][n0 + 1], adh[mt], wbh[2], wbh[3]);
                    mma_bf16(acc1[mt][n0 + 1], adl[mt], wbh[2], wbh[3]);
                    mma_bf16(acc1[mt][n0 + 1], adh[mt], wbl[2], wbl[3]);
                }
            }
            #pragma unroll
            for (int nb = 0; nb < 8; nb++) {
                int col = c0 + nb * 8 + (lid & 3) * 2;
                float A0 = smf[OFF_AS/4 + col], A1 = smf[OFF_AS/4 + col + 1];
                float C0 = smf[OFF_CS/4 + col], C1 = smf[OFF_CS/4 + col + 1];
                #pragma unroll
                for (int mt = 0; mt < 2; mt++) {
                    int row = t0w + mt * 16 + (lid >> 2);
                    float x0 = fmaxf(acc1[mt][nb][0] * A0 + C0, 0.f);
                    float x1 = fmaxf(acc1[mt][nb][1] * A1 + C1, 0.f);
                    float x2 = fmaxf(acc1[mt][nb][2] * A0 + C0, 0.f);
                    float x3 = fmaxf(acc1[mt][nb][3] * A1 + C1, 0.f);
                    float l0, l1, l2, l3;
                    uint32_t hiA = pack_hi(x0, x1, l0, l1);
                    uint32_t hiB = pack_hi(x2, x3, l2, l3);
                    *(uint32_t*)(sm + OFF_HHI + row * PBB + col * 2)       = hiA;
                    *(uint32_t*)(sm + OFF_HLO + row * PBB + col * 2)       = pack_bf(l0, l1);
                    *(uint32_t*)(sm + OFF_HHI + (row + 8) * PBB + col * 2) = hiB;
                    *(uint32_t*)(sm + OFF_HLO + (row + 8) * PBB + col * 2) = pack_bf(l2, l3);
                }
            }
        }
        __syncthreads();   // (c) h ready

        // ---- GEMM2: out = h @ W2 (split-bf16 HMMA) ----
        float acc[2][8][4];
        #pragma unroll
        for (int mt = 0; mt < 2; mt++)
            #pragma unroll
            for (int n = 0; n < 8; n++)
                #pragma unroll
                for (int j = 0; j < 4; j++) acc[mt][n][j] = 0.f;

        #pragma unroll 2
        for (int kk = 0; kk < 8; kk++) {
            uint32_t ah[2][4], al[2][4];
            ldm_x4(ah[0], aHi0 + kk * 32);
            ldm_x4(al[0], aHi0 + LO_A + kk * 32);
            ldm_x4(ah[1], aHi1 + kk * 32);
            ldm_x4(al[1], aHi1 + LO_A + kk * 32);
            uint32_t bkoff = (uint32_t)kk * 16 * PBB;
            #pragma unroll
            for (int nb2 = 0; nb2 < 4; nb2++) {
                uint32_t bh[4], bl[4];
                ldm_x4_t(bh, bBase + bkoff + nb2 * 32);
                ldm_x4_t(bl, bBase + LO_B + bkoff + nb2 * 32);
                int n0 = nb2 * 2;
                #pragma unroll
                for (int mt = 0; mt < 2; mt++) {
                    mma_bf16(acc[mt][n0],     ah[mt], bh[0], bh[1]);
                    mma_bf16(acc[mt][n0],     al[mt], bh[0], bh[1]);
                    mma_bf16(acc[mt][n0],     ah[mt], bl[0], bl[1]);
                    mma_bf16(acc[mt][n0 + 1], ah[mt], bh[2], bh[3]);
                    mma_bf16(acc[mt][n0 + 1], al[mt], bh[2], bh[3]);
                    mma_bf16(acc[mt][n0 + 1], ah[mt], bl[2], bl[3]);
                }
            }
        }

        // ---- epilogue: bias + mask, direct STG.64 from fragments ----
        #pragma unroll
        for (int mt = 0; mt < 2; mt++) {
            int row = t0w + mt * 16 + (lid >> 2);
            float m1 = smf[OFF_MS/4 + row];
            float m2 = smf[OFF_MS/4 + row + 8];
            float* o1 = &out[(size_t)(tok0 + row) * DD];
            float* o2 = &out[(size_t)(tok0 + row + 8) * DD];
            #pragma unroll
            for (int nt = 0; nt < 8; nt++) {
                int col = c0 + nt * 8 + (lid & 3) * 2;
                float b0 = smf[OFF_B2/4 + col], b1v = smf[OFF_B2/4 + col + 1];
                float2 v1 = make_float2((acc[mt][nt][0] + b0) * m1, (acc[mt][nt][1] + b1v) * m1);
                float2 v2 = make_float2((acc[mt][nt][2] + b0) * m2, (acc[mt][nt][3] + b1v) * m2);
                *(float2*)&o1[col] = v1;
                *(float2*)&o2[col] = v2;
            }
        }
        if (do_tail && tid < DD)
            out[(size_t)TOKENS * DD + tok0 + tid] = smf[OFF_MS/4 + tid];
    }
}

extern "C" void kernel_launch(void* const* d_in, const int* in_sizes, int n_in,
                              void* d_out, int out_size) {
    const float* diff  = (const float*)d_in[0];
    const int*   mask  = (const int*)d_in[1];
    const float* W1    = (const float*)d_in[2];
    const float* b1    = (const float*)d_in[3];
    const float* gamma = (const float*)d_in[4];
    const float* beta  = (const float*)d_in[5];
    const float* W2    = (const float*)d_in[6];
    const float* b2    = (const float*)d_in[7];
    float* out = (float*)d_out;
    int do_tail = (out_size > TOKENS * DD) ? 1 : 0;

    cudaFuncSetAttribute(k_main,   cudaFuncAttributeMaxDynamicSharedMemorySize, SMEM_MAIN);
    cudaFuncSetAttribute(k_stats2, cudaFuncAttributeMaxDynamicSharedMemorySize, SMEM_STAT);

    k_stats2<<<STAT_BLOCKS, 256, SMEM_STAT>>>(diff, mask);
    k_final2<<<1, 544>>>(W1, b1, gamma, beta);
    k_main<<<148, 256, SMEM_MAIN>>>(diff, mask, W1, W2, b2, out, do_tail);
}

// round 16
// speedup vs baseline: 4.9783x; 1.1645x over previous
#include <cuda_runtime.h>
#include <cuda_bf16.h>
#include <cuda_fp16.h>
#include <cstdint>

// ---------------- problem constants ----------------
#define TOKENS (8*128*256)        // 262144
#define CIN 15
#define DD 128
#define NTILES (TOKENS/DD)        // 2048 token tiles
#define PBB 272                   // h / W2 row pitch bytes (136 halves) -> conflict-free ldmatrix
#define DPB 48                    // diffB row pitch bytes (16 halves + pad)
#define W1PB 272                  // W1B row pitch bytes

// ---------------- k_main smem layout (bytes) ----------------
#define OFF_W2HI 0                // 128 x 136 f16 = 34816  (B for GEMM2, fp16-rounded)
#define OFF_HHI  34816            // h hi (128 tok x 136 f16)
#define OFF_HLO  69632            // h lo                  (ends 104448)
#define OFF_DBHI 104448           // diff hi 128 x 48B = 6144
#define OFF_DBLO 110592           // diff lo               (ends 116736)
#define OFF_W1HI 116736           // W1 hi 16 x 272B = 4352 (B for GEMM1, fp16-rounded)
#define OFF_MS   121088           // 128 f32
#define OFF_B2   121600
#define OFF_AS   122112
#define OFF_CS   122624
#define SMEM_MAIN 123136

// ---------------- k_stats smem layout (bytes) ----------------
#define SOFF_DS   0               // 512*15 f32 = 30720
#define SOFF_MSK  30720           // 512 f32
#define SOFF_UHI  32768           // 16 x 1040B (pitch 520 bf16)
#define SOFF_ULO  49408
#define SOFF_RED  66048           // 8 warps x 256 f32 = 8192
#define SMEM_STAT 74240
#define UPITCH 1040

__device__ __forceinline__ uint32_t smem_u32(const void* p) {
    uint32_t a;
    asm("{ .reg .u64 t; cvta.to.shared.u64 t, %1; cvt.u32.u64 %0, t; }" : "=r"(a) : "l"(p));
    return a;
}
__device__ __forceinline__ void ldm_x4(uint32_t* r, uint32_t addr) {
    asm volatile("ldmatrix.sync.aligned.m8n8.x4.shared.b16 {%0,%1,%2,%3}, [%4];"
                 : "=r"(r[0]), "=r"(r[1]), "=r"(r[2]), "=r"(r[3]) : "r"(addr));
}
__device__ __forceinline__ void ldm_x4_t(uint32_t* r, uint32_t addr) {
    asm volatile("ldmatrix.sync.aligned.m8n8.x4.trans.shared.b16 {%0,%1,%2,%3}, [%4];"
                 : "=r"(r[0]), "=r"(r[1]), "=r"(r[2]), "=r"(r[3]) : "r"(addr));
}
__device__ __forceinline__ void mma_bf16(float* d, const uint32_t* a, uint32_t b0, uint32_t b1) {
    asm volatile("mma.sync.aligned.m16n8k16.row.col.f32.bf16.bf16.f32 "
                 "{%0,%1,%2,%3}, {%4,%5,%6,%7}, {%8,%9}, {%0,%1,%2,%3};"
                 : "+f"(d[0]), "+f"(d[1]), "+f"(d[2]), "+f"(d[3])
                 : "r"(a[0]), "r"(a[1]), "r"(a[2]), "r"(a[3]), "r"(b0), "r"(b1));
}
__device__ __forceinline__ void mma_f16(float* d, const uint32_t* a, uint32_t b0, uint32_t b1) {
    asm volatile("mma.sync.aligned.m16n8k16.row.col.f32.f16.f16.f32 "
                 "{%0,%1,%2,%3}, {%4,%5,%6,%7}, {%8,%9}, {%0,%1,%2,%3};"
                 : "+f"(d[0]), "+f"(d[1]), "+f"(d[2]), "+f"(d[3])
                 : "r"(a[0]), "r"(a[1]), "r"(a[2]), "r"(a[3]), "r"(b0), "r"(b1));
}
// fp16 split helpers
__device__ __forceinline__ uint32_t packh2(float x0, float x1) {
    __half2 h = __floats2half2_rn(x0, x1);
    return *reinterpret_cast<uint32_t*>(&h);
}
__device__ __forceinline__ uint32_t pack_hi_f16(float x0, float x1, float& r0, float& r1) {
    __half h0 = __float2half_rn(x0), h1 = __float2half_rn(x1);
    r0 = x0 - __half2float(h0); r1 = x1 - __half2float(h1);
    return ((uint32_t)__half_as_ushort(h1) << 16) | __half_as_ushort(h0);
}

// ---------------- global scratch ----------------
#define NSTAT 136                      // su[15] + S_upper[120] + cnt
#define STAT_BLOCKS 512
__device__ float g_p2[STAT_BLOCKS * NSTAT];
__device__ float g_A[DD];
__device__ float g_C[DD];

// ===== Pass A: masked 2nd-moment matrix S = (mU)^T(mU) via split-bf16 HMMA =====
// (unchanged from R14 — verified at rel_err 6.4e-6)
__global__ void __launch_bounds__(256) k_stats2(const float* __restrict__ diff,
                                                const int* __restrict__ mask) {
    extern __shared__ char ssm[];
    float* ds  = (float*)(ssm + SOFF_DS);
    float* msk = (float*)(ssm + SOFF_MSK);
    float* red = (float*)(ssm + SOFF_RED);
    uint32_t smb = smem_u32(ssm);
    int tid = threadIdx.x, lid = tid & 31, w = tid >> 5;
    int tok0 = blockIdx.x * 512;

    for (int i = tid; i < 512 * CIN; i += 256) ds[i] = diff[(size_t)tok0 * CIN + i];
    for (int i = tid; i < 512; i += 256) msk[i] = mask[tok0 + i] ? 1.0f : 0.0f;
    __syncthreads();

    for (int idx = tid; idx < 16 * 512; idx += 256) {
        int c = idx >> 9, t = idx & 511;
        float m = msk[t];
        float v = (c < CIN) ? ds[t * CIN + c] * m : m;
        __nv_bfloat16 vh = __float2bfloat16(v);
        float lo = v - __bfloat162float(vh);
        *(__nv_bfloat16*)(ssm + SOFF_UHI + c * UPITCH + t * 2) = vh;
        *(__nv_bfloat16*)(ssm + SOFF_ULO + c * UPITCH + t * 2) = __float2bfloat16(lo);
    }
    __syncthreads();

    float accD[2][4] = {{0.f,0.f,0.f,0.f},{0.f,0.f,0.f,0.f}};
    {
        int g = lid >> 3, i8 = lid & 7;
        uint32_t frag = (uint32_t)(i8 + ((g & 1) << 3)) * UPITCH + ((g >> 1) << 4);
        #pragma unroll
        for (int ch = 0; ch < 4; ch++) {
            uint32_t toff = (uint32_t)(w * 64 + ch * 16) * 2;
            uint32_t uh[4], ul[4];
            ldm_x4(uh, smb + SOFF_UHI + frag + toff);
            ldm_x4(ul, smb + SOFF_ULO + frag + toff);
            mma_bf16(accD[0], uh, uh[0], uh[2]);
            mma_bf16(accD[0], ul, uh[0], uh[2]);
            mma_bf16(accD[0], uh, ul[0], ul[2]);
            mma_bf16(accD[1], uh, uh[1], uh[3]);
            mma_bf16(accD[1], ul, uh[1], uh[3]);
            mma_bf16(accD[1], uh, ul[1], ul[3]);
        }
    }
    {
        int i = lid >> 2, jq = (lid & 3) * 2;
        #pragma unroll
        for (int n = 0; n < 2; n++) {
            int j = n * 8 + jq;
            red[w * 256 + i * 16 + j]           = accD[n][0];
            red[w * 256 + i * 16 + j + 1]       = accD[n][1];
            red[w * 256 + (i + 8) * 16 + j]     = accD[n][2];
            red[w * 256 + (i + 8) * 16 + j + 1] = accD[n][3];
        }
    }
    __syncthreads();
    {
        int i = tid >> 4, j = tid & 15;
        int slot = -1;
        if (i == 15 && j == 15) slot = 135;
        else if (j == 15 && i < 15) slot = i;
        else if (i <= j && j < 15) slot = 15 + i * 15 - (i * (i - 1)) / 2 + (j - i);
        if (slot >= 0) {
            float s = 0.f;
            #pragma unroll
            for (int ww = 0; ww < 8; ww++) s += red[ww * 256 + i * 16 + j];
            g_p2[blockIdx.x * NSTAT + slot] = s;
        }
    }
}

// ================= Pass B: finalize BN affine (unchanged) =================
__global__ void __launch_bounds__(544) k_final2(const float* __restrict__ W1,
                                                const float* __restrict__ b1,
                                                const float* __restrict__ gamma,
                                                const float* __restrict__ beta) {
    __shared__ float part[4 * NSTAT];
    __shared__ float tot[NSTAT];
    __shared__ float Sf[CIN][CIN];
    __shared__ float suS[CIN];
    __shared__ float cntS;
    int tid = threadIdx.x;
    {
        int grp = tid / NSTAT, j = tid - grp * NSTAT;
        float s = 0.f;
        for (int b = grp; b < STAT_BLOCKS; b += 4) s += g_p2[b * NSTAT + j];
        part[grp * NSTAT + j] = s;
    }
    __syncthreads();
    if (tid < NSTAT)
        tot[tid] = part[tid] + part[NSTAT + tid] + part[2 * NSTAT + tid] + part[3 * NSTAT + tid];
    __syncthreads();
    if (tid < CIN * CIN) {
        int i = tid / CIN, j = tid % CIN;
        int a = i < j ? i : j, b = i < j ? j : i;
        Sf[i][j] = tot[CIN + a * CIN - (a * (a - 1)) / 2 + (b - a)];
    }
    if (tid < CIN) suS[tid] = tot[tid];
    if (tid == 0) cntS = tot[135];
    __syncthreads();
    if (tid < DD) {
        int d = tid;
        float w[CIN];
        #pragma unroll
        for (int c = 0; c < CIN; c++) w[c] = W1[c * DD + d];
        float sh = 0.f;
        #pragma unroll
        for (int c = 0; c < CIN; c++) sh += suS[c] * w[c];
        float q = 0.f;
        #pragma unroll
        for (int i = 0; i < CIN; i++) {
            float acc = 0.f;
            #pragma unroll
            for (int j = 0; j < CIN; j++) acc += Sf[i][j] * w[j];
            q += w[i] * acc;
        }
        float cnt = fmaxf(cntS, 1.f);
        float bb = b1[d];
        float mean = (sh + cnt * bb) / cnt;
        float sum2 = q + 2.f * bb * sh + cnt * bb * bb;
        float var = fmaxf(sum2 / cnt - mean * mean, 0.f);
        float A = gamma[d] * rsqrtf(var + 1e-5f);
        g_A[d] = A;
        g_C[d] = beta[d] + (bb - mean) * A;
    }
}

// ========== Pass C (persistent): fp16 2-product HMMA GEMM1 + GEMM2 ==========
// a*b ~= (a_hi + a_lo) * fp16(b): A split into fp16 hi/lo (2 products), B rounded.
__global__ void __launch_bounds__(256, 1) k_main(
        const float* __restrict__ diff, const int* __restrict__ mask,
        const float* __restrict__ W1, const float* __restrict__ W2,
        const float* __restrict__ b2, float* __restrict__ out, int do_tail) {
    extern __shared__ char sm[];
    float* smf = (float*)sm;
    uint32_t smb = smem_u32(sm);
    int tid = threadIdx.x, lid = tid & 31, wid = tid >> 5;

    // --- once per CTA: W2 -> fp16 (B of GEMM2), W1 -> fp16 (B of GEMM1, K padded to 16) ---
    for (int idx = tid; idx < DD * DD; idx += 256) {
        int d = idx >> 7, e = idx & 127;
        *(__half*)(sm + OFF_W2HI + d * PBB + e * 2) = __float2half_rn(W2[idx]);
    }
    for (int idx = tid; idx < 16 * DD; idx += 256) {
        int k = idx >> 7, n = idx & 127;
        float v = (k < CIN) ? W1[k * DD + n] : 0.f;
        *(__half*)(sm + OFF_W1HI + k * W1PB + n * 2) = __float2half_rn(v);
    }
    if (tid < DD) {
        smf[OFF_B2/4 + tid] = b2[tid];
        smf[OFF_AS/4 + tid] = g_A[tid];
        smf[OFF_CS/4 + tid] = g_C[tid];
    }

    // warp tile: 32 tokens x 64 channels (both GEMMs)
    int wt = wid >> 1;
    int c0 = (wid & 1) * 64;
    int t0w = wt * 32;
    int g = lid >> 3, i8 = lid & 7;
    uint32_t aHi0 = smb + OFF_HHI + (uint32_t)(t0w + i8 + ((g & 1) << 3)) * PBB + ((g >> 1) << 4);
    uint32_t aHi1 = aHi0 + 16 * PBB;
    uint32_t bBase = smb + OFF_W2HI + (uint32_t)(i8 + ((g & 1) << 3)) * PBB
                   + ((uint32_t)c0 << 1) + ((g >> 1) << 4);
    const uint32_t LO_A = OFF_HLO - OFF_HHI;
    uint32_t aD0 = smb + OFF_DBHI + (uint32_t)(t0w + i8 + ((g & 1) << 3)) * DPB + ((g >> 1) << 4);
    uint32_t wB  = smb + OFF_W1HI + (uint32_t)(i8 + ((g & 1) << 3)) * W1PB
                 + ((uint32_t)c0 << 1) + ((g >> 1) << 4);
    const uint32_t LO_D = OFF_DBLO - OFF_DBHI;

    for (int tile = blockIdx.x; tile < NTILES; tile += gridDim.x) {
        int tok0 = tile * DD;
        __syncthreads();   // (a) protect MS/diffB against prev-iter readers

        // stage diff tile as split fp16 (K padded to 16); mask
        for (int idx = tid; idx < DD * 16; idx += 256) {
            int t = idx >> 4, c = idx & 15;
            float v = (c < CIN) ? diff[(size_t)(tok0 + t) * CIN + c] : 0.f;
            __half vh = __float2half_rn(v);
            float lo = v - __half2float(vh);
            *(__half*)(sm + OFF_DBHI + t * DPB + c * 2) = vh;
            *(__half*)(sm + OFF_DBLO + t * DPB + c * 2) = __float2half_rn(lo);
        }
        if (tid < DD) smf[OFF_MS/4 + tid] = mask[tok0 + tid] ? 1.0f : 0.0f;
        __syncthreads();   // (b) diffB/MS ready

        // ---- GEMM1: h = diff @ W1 (fp16 2-product), BN+ReLU+split -> h smem ----
        {
            float acc1[2][8][4];
            #pragma unroll
            for (int mt = 0; mt < 2; mt++)
                #pragma unroll
                for (int n = 0; n < 8; n++)
                    #pragma unroll
                    for (int j = 0; j < 4; j++) acc1[mt][n][j] = 0.f;

            uint32_t adh[2][4], adl[2][4];
            ldm_x4(adh[0], aD0);
            ldm_x4(adl[0], aD0 + LO_D);
            ldm_x4(adh[1], aD0 + 16 * DPB);
            ldm_x4(adl[1], aD0 + 16 * DPB + LO_D);
            #pragma unroll
            for (int nb2 = 0; nb2 < 4; nb2++) {
                uint32_t wbh[4];
                ldm_x4_t(wbh, wB + nb2 * 32);
                int n0 = nb2 * 2;
                #pragma unroll
                for (int mt = 0; mt < 2; mt++) {
                    mma_f16(acc1[mt][n0],     adh[mt], wbh[0], wbh[1]);
                    mma_f16(acc1[mt][n0],     adl[mt], wbh[0], wbh[1]);
                    mma_f16(acc1[mt][n0 + 1], adh[mt], wbh[2], wbh[3]);
                    mma_f16(acc1[mt][n0 + 1], adl[mt], wbh[2], wbh[3]);
                }
            }
            #pragma unroll
            for (int nb = 0; nb < 8; nb++) {
                int col = c0 + nb * 8 + (lid & 3) * 2;
                float A0 = smf[OFF_AS/4 + col], A1 = smf[OFF_AS/4 + col + 1];
                float C0 = smf[OFF_CS/4 + col], C1 = smf[OFF_CS/4 + col + 1];
                #pragma unroll
                for (int mt = 0; mt < 2; mt++) {
                    int row = t0w + mt * 16 + (lid >> 2);
                    float x0 = fmaxf(acc1[mt][nb][0] * A0 + C0, 0.f);
                    float x1 = fmaxf(acc1[mt][nb][1] * A1 + C1, 0.f);
                    float x2 = fmaxf(acc1[mt][nb][2] * A0 + C0, 0.f);
                    float x3 = fmaxf(acc1[mt][nb][3] * A1 + C1, 0.f);
                    float l0, l1, l2, l3;
                    uint32_t hiA = pack_hi_f16(x0, x1, l0, l1);
                    uint32_t hiB = pack_hi_f16(x2, x3, l2, l3);
                    *(uint32_t*)(sm + OFF_HHI + row * PBB + col * 2)       = hiA;
                    *(uint32_t*)(sm + OFF_HLO + row * PBB + col * 2)       = packh2(l0, l1);
                    *(uint32_t*)(sm + OFF_HHI + (row + 8) * PBB + col * 2) = hiB;
                    *(uint32_t*)(sm + OFF_HLO + (row + 8) * PBB + col * 2) = packh2(l2, l3);
                }
            }
        }
        __syncthreads();   // (c) h ready

        // ---- GEMM2: out = h @ W2 (fp16 2-product) ----
        float acc[2][8][4];
        #pragma unroll
        for (int mt = 0; mt < 2; mt++)
            #pragma unroll
            for (int n = 0; n < 8; n++)
                #pragma unroll
                for (int j = 0; j < 4; j++) acc[mt][n][j] = 0.f;

        #pragma unroll 2
        for (int kk = 0; kk < 8; kk++) {
            uint32_t ah[2][4], al[2][4];
            ldm_x4(ah[0], aHi0 + kk * 32);
            ldm_x4(al[0], aHi0 + LO_A + kk * 32);
            ldm_x4(ah[1], aHi1 + kk * 32);
            ldm_x4(al[1], aHi1 + LO_A + kk * 32);
            uint32_t bkoff = (uint32_t)kk * 16 * PBB;
            #pragma unroll
            for (int nb2 = 0; nb2 < 4; nb2++) {
                uint32_t bh[4];
                ldm_x4_t(bh, bBase + bkoff + nb2 * 32);
                int n0 = nb2 * 2;
                #pragma unroll
                for (int mt = 0; mt < 2; mt++) {
                    mma_f16(acc[mt][n0],     ah[mt], bh[0], bh[1]);
                    mma_f16(acc[mt][n0],     al[mt], bh[0], bh[1]);
                    mma_f16(acc[mt][n0 + 1], ah[mt], bh[2], bh[3]);
                    mma_f16(acc[mt][n0 + 1], al[mt], bh[2], bh[3]);
                }
            }
        }

        // ---- epilogue: bias + mask, direct STG.64 from fragments ----
        #pragma unroll
        for (int mt = 0; mt < 2; mt++) {
            int row = t0w + mt * 16 + (lid >> 2);
            float m1 = smf[OFF_MS/4 + row];
            float m2 = smf[OFF_MS/4 + row + 8];
            float* o1 = &out[(size_t)(tok0 + row) * DD];
            float* o2 = &out[(size_t)(tok0 + row + 8) * DD];
            #pragma unroll
            for (int nt = 0; nt < 8; nt++) {
                int col = c0 + nt * 8 + (lid & 3) * 2;
                float b0 = smf[OFF_B2/4 + col], b1v = smf[OFF_B2/4 + col + 1];
                float2 v1 = make_float2((acc[mt][nt][0] + b0) * m1, (acc[mt][nt][1] + b1v) * m1);
                float2 v2 = make_float2((acc[mt][nt][2] + b0) * m2, (acc[mt][nt][3] + b1v) * m2);
                *(float2*)&o1[col] = v1;
                *(float2*)&o2[col] = v2;
            }
        }
        if (do_tail && tid < DD)
            out[(size_t)TOKENS * DD + tok0 + tid] = smf[OFF_MS/4 + tid];
    }
}

extern "C" void kernel_launch(void* const* d_in, const int* in_sizes, int n_in,
                              void* d_out, int out_size) {
    const float* diff  = (const float*)d_in[0];
    const int*   mask  = (const int*)d_in[1];
    const float* W1    = (const float*)d_in[2];
    const float* b1    = (const float*)d_in[3];
    const float* gamma = (const float*)d_in[4];
    const float* beta  = (const float*)d_in[5];
    const float* W2    = (const float*)d_in[6];
    const float* b2    = (const float*)d_in[7];
    float* out = (float*)d_out;
    int do_tail = (out_size > TOKENS * DD) ? 1 : 0;

    cudaFuncSetAttribute(k_main,   cudaFuncAttributeMaxDynamicSharedMemorySize, SMEM_MAIN);
    cudaFuncSetAttribute(k_stats2, cudaFuncAttributeMaxDynamicSharedMemorySize, SMEM_STAT);

    k_stats2<<<STAT_BLOCKS, 256, SMEM_STAT>>>(diff, mask);
    k_final2<<<1, 544>>>(W1, b1, gamma, beta);
    k_main<<<148, 256, SMEM_MAIN>>>(diff, mask, W1, W2, b2, out, do_tail);
}

// round 17
// speedup vs baseline: 5.5508x; 1.1150x over previous
#include <cuda_runtime.h>
#include <cuda_bf16.h>
#include <cuda_fp16.h>
#include <cstdint>

// ---------------- problem constants ----------------
#define TOKENS (8*128*256)        // 262144
#define CIN 15
#define DD 128
#define NTILES (TOKENS/DD)        // 2048 token tiles
#define PBB 272                   // h / W2 row pitch bytes (136 halves) -> conflict-free ldmatrix
#define DPB 48                    // diffB row pitch bytes (16 halves + pad)
#define W1PB 272                  // W1B row pitch bytes

// ---------------- k_main smem layout (bytes) ----------------
#define OFF_W2HI 0                // 128 x 136 f16 = 34816  (B for GEMM2, fp16-rounded)
#define OFF_HHI  34816            // h hi (128 tok x 136 f16)
#define OFF_HLO  69632            // h lo                  (ends 104448)
#define OFF_DBHI 104448           // diff hi 128 x 48B = 6144
#define OFF_DBLO 110592           // diff lo               (ends 116736)
#define OFF_W1HI 116736           // W1 hi 16 x 272B = 4352 (B for GEMM1, fp16-rounded)
#define OFF_MS   121088           // 128 f32
#define OFF_B2   121600
#define OFF_AS   122112
#define OFF_CS   122624
#define SMEM_MAIN 123136

// ---------------- k_stats smem layout (bytes), 256 tokens/block ----------------
#define STOK 256
#define SOFF_DS   0               // 256*15 f32 = 15360
#define SOFF_MSK  15360           // 256 f32 (pad to 1024)
#define SOFF_UHI  16384           // 16 x 528B = 8448
#define SOFF_ULO  24832           // 8448 (ends 33280)
#define SOFF_RED  33280           // 8 warps x 256 f32 = 8192
#define SMEM_STAT 41472
#define UPITCH 528

__device__ __forceinline__ uint32_t smem_u32(const void* p) {
    uint32_t a;
    asm("{ .reg .u64 t; cvta.to.shared.u64 t, %1; cvt.u32.u64 %0, t; }" : "=r"(a) : "l"(p));
    return a;
}
__device__ __forceinline__ void ldm_x4(uint32_t* r, uint32_t addr) {
    asm volatile("ldmatrix.sync.aligned.m8n8.x4.shared.b16 {%0,%1,%2,%3}, [%4];"
                 : "=r"(r[0]), "=r"(r[1]), "=r"(r[2]), "=r"(r[3]) : "r"(addr));
}
__device__ __forceinline__ void ldm_x4_t(uint32_t* r, uint32_t addr) {
    asm volatile("ldmatrix.sync.aligned.m8n8.x4.trans.shared.b16 {%0,%1,%2,%3}, [%4];"
                 : "=r"(r[0]), "=r"(r[1]), "=r"(r[2]), "=r"(r[3]) : "r"(addr));
}
__device__ __forceinline__ void mma_bf16(float* d, const uint32_t* a, uint32_t b0, uint32_t b1) {
    asm volatile("mma.sync.aligned.m16n8k16.row.col.f32.bf16.bf16.f32 "
                 "{%0,%1,%2,%3}, {%4,%5,%6,%7}, {%8,%9}, {%0,%1,%2,%3};"
                 : "+f"(d[0]), "+f"(d[1]), "+f"(d[2]), "+f"(d[3])
                 : "r"(a[0]), "r"(a[1]), "r"(a[2]), "r"(a[3]), "r"(b0), "r"(b1));
}
__device__ __forceinline__ void mma_f16(float* d, const uint32_t* a, uint32_t b0, uint32_t b1) {
    asm volatile("mma.sync.aligned.m16n8k16.row.col.f32.f16.f16.f32 "
                 "{%0,%1,%2,%3}, {%4,%5,%6,%7}, {%8,%9}, {%0,%1,%2,%3};"
                 : "+f"(d[0]), "+f"(d[1]), "+f"(d[2]), "+f"(d[3])
                 : "r"(a[0]), "r"(a[1]), "r"(a[2]), "r"(a[3]), "r"(b0), "r"(b1));
}
__device__ __forceinline__ uint32_t packh2(float x0, float x1) {
    __half2 h = __floats2half2_rn(x0, x1);
    return *reinterpret_cast<uint32_t*>(&h);
}
__device__ __forceinline__ uint32_t pack_hi_f16(float x0, float x1, float& r0, float& r1) {
    __half h0 = __float2half_rn(x0), h1 = __float2half_rn(x1);
    r0 = x0 - __half2float(h0); r1 = x1 - __half2float(h1);
    return ((uint32_t)__half_as_ushort(h1) << 16) | __half_as_ushort(h0);
}

// ---------------- global scratch ----------------
#define NSTAT 136                      // su[15] + S_upper[120] + cnt
#define STAT_BLOCKS 1024               // 256 tokens each
__device__ float g_p2[STAT_BLOCKS * NSTAT];
__device__ float g_A[DD];
__device__ float g_C[DD];

// ===== Pass A: masked 2nd-moment matrix S = (mU)^T(mU) via split-bf16 HMMA =====
// 256 tokens/block, float4 loads, 41.5KB smem (5 CTAs/SM). Fragment math identical
// to the verified 512-token version; only block size / pitch changed.
__global__ void __launch_bounds__(256) k_stats2(const float* __restrict__ diff,
                                                const int* __restrict__ mask) {
    extern __shared__ char ssm[];
    float* ds  = (float*)(ssm + SOFF_DS);
    float* msk = (float*)(ssm + SOFF_MSK);
    float* red = (float*)(ssm + SOFF_RED);
    uint32_t smb = smem_u32(ssm);
    int tid = threadIdx.x, lid = tid & 31, w = tid >> 5;
    int tok0 = blockIdx.x * STOK;

    // vectorized load: 256*15 floats = 960 float4
    {
        const float4* dsrc = (const float4*)(diff + (size_t)tok0 * CIN);
        for (int i = tid; i < STOK * CIN / 4; i += 256) ((float4*)ds)[i] = dsrc[i];
        msk[tid] = mask[tok0 + tid] ? 1.0f : 0.0f;
    }
    __syncthreads();

    // transpose + mask + split to bf16 hi/lo: U[16 feat][256 tok]
    for (int idx = tid; idx < 16 * STOK; idx += 256) {
        int c = idx >> 8, t = idx & (STOK - 1);
        float m = msk[t];
        float v = (c < CIN) ? ds[t * CIN + c] * m : m;
        __nv_bfloat16 vh = __float2bfloat16(v);
        float lo = v - __bfloat162float(vh);
        *(__nv_bfloat16*)(ssm + SOFF_UHI + c * UPITCH + t * 2) = vh;
        *(__nv_bfloat16*)(ssm + SOFF_ULO + c * UPITCH + t * 2) = __float2bfloat16(lo);
    }
    __syncthreads();

    // warp w: tokens [w*32, w*32+32), 2 chunks of 16
    float accD[2][4] = {{0.f,0.f,0.f,0.f},{0.f,0.f,0.f,0.f}};
    {
        int g = lid >> 3, i8 = lid & 7;
        uint32_t frag = (uint32_t)(i8 + ((g & 1) << 3)) * UPITCH + ((g >> 1) << 4);
        #pragma unroll
        for (int ch = 0; ch < 2; ch++) {
            uint32_t toff = (uint32_t)(w * 32 + ch * 16) * 2;
            uint32_t uh[4], ul[4];
            ldm_x4(uh, smb + SOFF_UHI + frag + toff);
            ldm_x4(ul, smb + SOFF_ULO + frag + toff);
            mma_bf16(accD[0], uh, uh[0], uh[2]);
            mma_bf16(accD[0], ul, uh[0], uh[2]);
            mma_bf16(accD[0], uh, ul[0], ul[2]);
            mma_bf16(accD[1], uh, uh[1], uh[3]);
            mma_bf16(accD[1], ul, uh[1], uh[3]);
            mma_bf16(accD[1], uh, ul[1], ul[3]);
        }
    }
    {
        int i = lid >> 2, jq = (lid & 3) * 2;
        #pragma unroll
        for (int n = 0; n < 2; n++) {
            int j = n * 8 + jq;
            red[w * 256 + i * 16 + j]           = accD[n][0];
            red[w * 256 + i * 16 + j + 1]       = accD[n][1];
            red[w * 256 + (i + 8) * 16 + j]     = accD[n][2];
            red[w * 256 + (i + 8) * 16 + j + 1] = accD[n][3];
        }
    }
    __syncthreads();
    {
        int i = tid >> 4, j = tid & 15;
        int slot = -1;
        if (i == 15 && j == 15) slot = 135;
        else if (j == 15 && i < 15) slot = i;
        else if (i <= j && j < 15) slot = 15 + i * 15 - (i * (i - 1)) / 2 + (j - i);
        if (slot >= 0) {
            float s = 0.f;
            #pragma unroll
            for (int ww = 0; ww < 8; ww++) s += red[ww * 256 + i * 16 + j];
            g_p2[blockIdx.x * NSTAT + slot] = s;
        }
    }
}

// ================= Pass B: finalize BN affine =================
__global__ void __launch_bounds__(544) k_final2(const float* __restrict__ W1,
                                                const float* __restrict__ b1,
                                                const float* __restrict__ gamma,
                                                const float* __restrict__ beta) {
    __shared__ float part[4 * NSTAT];
    __shared__ float tot[NSTAT];
    __shared__ float Sf[CIN][CIN];
    __shared__ float suS[CIN];
    __shared__ float cntS;
    int tid = threadIdx.x;
    {
        int grp = tid / NSTAT, j = tid - grp * NSTAT;
        float s = 0.f;
        for (int b = grp; b < STAT_BLOCKS; b += 4) s += g_p2[b * NSTAT + j];
        part[grp * NSTAT + j] = s;
    }
    __syncthreads();
    if (tid < NSTAT)
        tot[tid] = part[tid] + part[NSTAT + tid] + part[2 * NSTAT + tid] + part[3 * NSTAT + tid];
    __syncthreads();
    if (tid < CIN * CIN) {
        int i = tid / CIN, j = tid % CIN;
        int a = i < j ? i : j, b = i < j ? j : i;
        Sf[i][j] = tot[CIN + a * CIN - (a * (a - 1)) / 2 + (b - a)];
    }
    if (tid < CIN) suS[tid] = tot[tid];
    if (tid == 0) cntS = tot[135];
    __syncthreads();
    if (tid < DD) {
        int d = tid;
        float w[CIN];
        #pragma unroll
        for (int c = 0; c < CIN; c++) w[c] = W1[c * DD + d];
        float sh = 0.f;
        #pragma unroll
        for (int c = 0; c < CIN; c++) sh += suS[c] * w[c];
        float q = 0.f;
        #pragma unroll
        for (int i = 0; i < CIN; i++) {
            float acc = 0.f;
            #pragma unroll
            for (int j = 0; j < CIN; j++) acc += Sf[i][j] * w[j];
            q += w[i] * acc;
        }
        float cnt = fmaxf(cntS, 1.f);
        float bb = b1[d];
        float mean = (sh + cnt * bb) / cnt;
        float sum2 = q + 2.f * bb * sh + cnt * bb * bb;
        float var = fmaxf(sum2 / cnt - mean * mean, 0.f);
        float A = gamma[d] * rsqrtf(var + 1e-5f);
        g_A[d] = A;
        g_C[d] = beta[d] + (bb - mean) * A;
    }
}

// ========== Pass C (persistent): fp16 2-product HMMA, prefetch-pipelined ==========
__global__ void __launch_bounds__(256, 1) k_main(
        const float* __restrict__ diff, const int* __restrict__ mask,
        const float* __restrict__ W1, const float* __restrict__ W2,
        const float* __restrict__ b2, float* __restrict__ out, int do_tail) {
    extern __shared__ char sm[];
    float* smf = (float*)sm;
    uint32_t smb = smem_u32(sm);
    int tid = threadIdx.x, lid = tid & 31, wid = tid >> 5;

    // --- once per CTA: W2 -> fp16, W1 -> fp16 (K padded to 16) ---
    for (int idx = tid; idx < DD * DD; idx += 256) {
        int d = idx >> 7, e = idx & 127;
        *(__half*)(sm + OFF_W2HI + d * PBB + e * 2) = __float2half_rn(W2[idx]);
    }
    for (int idx = tid; idx < 16 * DD; idx += 256) {
        int k = idx >> 7, n = idx & 127;
        float v = (k < CIN) ? W1[k * DD + n] : 0.f;
        *(__half*)(sm + OFF_W1HI + k * W1PB + n * 2) = __float2half_rn(v);
    }
    if (tid < DD) {
        smf[OFF_B2/4 + tid] = b2[tid];
        smf[OFF_AS/4 + tid] = g_A[tid];
        smf[OFF_CS/4 + tid] = g_C[tid];
    }

    // warp tile: 32 tokens x 64 channels (both GEMMs)
    int wt = wid >> 1;
    int c0 = (wid & 1) * 64;
    int t0w = wt * 32;
    int g = lid >> 3, i8 = lid & 7;
    uint32_t aHi0 = smb + OFF_HHI + (uint32_t)(t0w + i8 + ((g & 1) << 3)) * PBB + ((g >> 1) << 4);
    uint32_t aHi1 = aHi0 + 16 * PBB;
    uint32_t bBase = smb + OFF_W2HI + (uint32_t)(i8 + ((g & 1) << 3)) * PBB
                   + ((uint32_t)c0 << 1) + ((g >> 1) << 4);
    const uint32_t LO_A = OFF_HLO - OFF_HHI;
    uint32_t aD0 = smb + OFF_DBHI + (uint32_t)(t0w + i8 + ((g & 1) << 3)) * DPB + ((g >> 1) << 4);
    uint32_t wB  = smb + OFF_W1HI + (uint32_t)(i8 + ((g & 1) << 3)) * W1PB
                 + ((uint32_t)c0 << 1) + ((g >> 1) << 4);
    const uint32_t LO_D = OFF_DBLO - OFF_DBHI;

    // --- prefetch state: 8 diff floats + 1 mask per thread ---
    float pfv[8];
    float pmv = 0.f;
    int tile0 = blockIdx.x;
    if (tile0 < NTILES) {
        int tok0 = tile0 * DD;
        #pragma unroll
        for (int i = 0; i < 8; i++) {
            int idx = tid + i * 256;
            int t = idx >> 4, c = idx & 15;
            pfv[i] = (c < CIN) ? __ldg(&diff[(size_t)(tok0 + t) * CIN + c]) : 0.f;
        }
        if (tid < DD) pmv = mask[tok0 + tid] ? 1.0f : 0.0f;
    }

    for (int tile = tile0; tile < NTILES; tile += gridDim.x) {
        int tok0 = tile * DD;
        __syncthreads();   // (a) prev-iter readers of MS/diffB done

        // stage prefetched diff as split fp16 + mask
        #pragma unroll
        for (int i = 0; i < 8; i++) {
            int idx = tid + i * 256;
            int t = idx >> 4, c = idx & 15;
            float v = pfv[i];
            __half vh = __float2half_rn(v);
            float lo = v - __half2float(vh);
            *(__half*)(sm + OFF_DBHI + t * DPB + c * 2) = vh;
            *(__half*)(sm + OFF_DBLO + t * DPB + c * 2) = __float2half_rn(lo);
        }
        if (tid < DD) smf[OFF_MS/4 + tid] = pmv;

        // issue next tile's gmem loads now; latency hides under GEMM1+GEMM2
        int ntile = tile + gridDim.x;
        if (ntile < NTILES) {
            int ntok0 = ntile * DD;
            #pragma unroll
            for (int i = 0; i < 8; i++) {
                int idx = tid + i * 256;
                int t = idx >> 4, c = idx & 15;
                pfv[i] = (c < CIN) ? __ldg(&diff[(size_t)(ntok0 + t) * CIN + c]) : 0.f;
            }
            if (tid < DD) pmv = mask[ntok0 + tid] ? 1.0f : 0.0f;
        }
        __syncthreads();   // (b) diffB/MS ready

        // ---- GEMM1: h = diff @ W1 (fp16 2-product), BN+ReLU+split -> h smem ----
        {
            float acc1[2][8][4];
            #pragma unroll
            for (int mt = 0; mt < 2; mt++)
                #pragma unroll
                for (int n = 0; n < 8; n++)
                    #pragma unroll
                    for (int j = 0; j < 4; j++) acc1[mt][n][j] = 0.f;

            uint32_t adh[2][4], adl[2][4];
            ldm_x4(adh[0], aD0);
            ldm_x4(adl[0], aD0 + LO_D);
            ldm_x4(adh[1], aD0 + 16 * DPB);
            ldm_x4(adl[1], aD0 + 16 * DPB + LO_D);
            #pragma unroll
            for (int nb2 = 0; nb2 < 4; nb2++) {
                uint32_t wbh[4];
                ldm_x4_t(wbh, wB + nb2 * 32);
                int n0 = nb2 * 2;
                #pragma unroll
                for (int mt = 0; mt < 2; mt++) {
                    mma_f16(acc1[mt][n0],     adh[mt], wbh[0], wbh[1]);
                    mma_f16(acc1[mt][n0],     adl[mt], wbh[0], wbh[1]);
                    mma_f16(acc1[mt][n0 + 1], adh[mt], wbh[2], wbh[3]);
                    mma_f16(acc1[mt][n0 + 1], adl[mt], wbh[2], wbh[3]);
                }
            }
            #pragma unroll
            for (int nb = 0; nb < 8; nb++) {
                int col = c0 + nb * 8 + (lid & 3) * 2;
                float A0 = smf[OFF_AS/4 + col], A1 = smf[OFF_AS/4 + col + 1];
                float C0 = smf[OFF_CS/4 + col], C1 = smf[OFF_CS/4 + col + 1];
                #pragma unroll
                for (int mt = 0; mt < 2; mt++) {
                    int row = t0w + mt * 16 + (lid >> 2);
                    float x0 = fmaxf(acc1[mt][nb][0] * A0 + C0, 0.f);
                    float x1 = fmaxf(acc1[mt][nb][1] * A1 + C1, 0.f);
                    float x2 = fmaxf(acc1[mt][nb][2] * A0 + C0, 0.f);
                    float x3 = fmaxf(acc1[mt][nb][3] * A1 + C1, 0.f);
                    float l0, l1, l2, l3;
                    uint32_t hiA = pack_hi_f16(x0, x1, l0, l1);
                    uint32_t hiB = pack_hi_f16(x2, x3, l2, l3);
                    *(uint32_t*)(sm + OFF_HHI + row * PBB + col * 2)       = hiA;
                    *(uint32_t*)(sm + OFF_HLO + row * PBB + col * 2)       = packh2(l0, l1);
                    *(uint32_t*)(sm + OFF_HHI + (row + 8) * PBB + col * 2) = hiB;
                    *(uint32_t*)(sm + OFF_HLO + (row + 8) * PBB + col * 2) = packh2(l2, l3);
                }
            }
        }
        __syncthreads();   // (c) h ready

        // ---- GEMM2: out = h @ W2 (fp16 2-product) ----
        float acc[2][8][4];
        #pragma unroll
        for (int mt = 0; mt < 2; mt++)
            #pragma unroll
            for (int n = 0; n < 8; n++)
                #pragma unroll
                for (int j = 0; j < 4; j++) acc[mt][n][j] = 0.f;

        #pragma unroll 2
        for (int kk = 0; kk < 8; kk++) {
            uint32_t ah[2][4], al[2][4];
            ldm_x4(ah[0], aHi0 + kk * 32);
            ldm_x4(al[0], aHi0 + LO_A + kk * 32);
            ldm_x4(ah[1], aHi1 + kk * 32);
            ldm_x4(al[1], aHi1 + LO_A + kk * 32);
            uint32_t bkoff = (uint32_t)kk * 16 * PBB;
            #pragma unroll
            for (int nb2 = 0; nb2 < 4; nb2++) {
                uint32_t bh[4];
                ldm_x4_t(bh, bBase + bkoff + nb2 * 32);
                int n0 = nb2 * 2;
                #pragma unroll
                for (int mt = 0; mt < 2; mt++) {
                    mma_f16(acc[mt][n0],     ah[mt], bh[0], bh[1]);
                    mma_f16(acc[mt][n0],     al[mt], bh[0], bh[1]);
                    mma_f16(acc[mt][n0 + 1], ah[mt], bh[2], bh[3]);
                    mma_f16(acc[mt][n0 + 1], al[mt], bh[2], bh[3]);
                }
            }
        }

        // ---- epilogue: bias + mask, direct STG.64 from fragments ----
        #pragma unroll
        for (int mt = 0; mt < 2; mt++) {
            int row = t0w + mt * 16 + (lid >> 2);
            float m1 = smf[OFF_MS/4 + row];
            float m2 = smf[OFF_MS/4 + row + 8];
            float* o1 = &out[(size_t)(tok0 + row) * DD];
            float* o2 = &out[(size_t)(tok0 + row + 8) * DD];
            #pragma unroll
            for (int nt = 0; nt < 8; nt++) {
                int col = c0 + nt * 8 + (lid & 3) * 2;
                float b0 = smf[OFF_B2/4 + col], b1v = smf[OFF_B2/4 + col + 1];
                float2 v1 = make_float2((acc[mt][nt][0] + b0) * m1, (acc[mt][nt][1] + b1v) * m1);
                float2 v2 = make_float2((acc[mt][nt][2] + b0) * m2, (acc[mt][nt][3] + b1v) * m2);
                *(float2*)&o1[col] = v1;
                *(float2*)&o2[col] = v2;
            }
        }
        if (do_tail && tid < DD)
            out[(size_t)TOKENS * DD + tok0 + tid] = smf[OFF_MS/4 + tid];
    }
}

extern "C" void kernel_launch(void* const* d_in, const int* in_sizes, int n_in,
                              void* d_out, int out_size) {
    const float* diff  = (const float*)d_in[0];
    const int*   mask  = (const int*)d_in[1];
    const float* W1    = (const float*)d_in[2];
    const float* b1    = (const float*)d_in[3];
    const float* gamma = (const float*)d_in[4];
    const float* beta  = (const float*)d_in[5];
    const float* W2    = (const float*)d_in[6];
    const float* b2    = (const float*)d_in[7];
    float* out = (float*)d_out;
    int do_tail = (out_size > TOKENS * DD) ? 1 : 0;

    cudaFuncSetAttribute(k_main,   cudaFuncAttributeMaxDynamicSharedMemorySize, SMEM_MAIN);
    cudaFuncSetAttribute(k_stats2, cudaFuncAttributeMaxDynamicSharedMemorySize, SMEM_STAT);

    k_stats2<<<STAT_BLOCKS, 256, SMEM_STAT>>>(diff, mask);
    k_final2<<<1, 544>>>(W1, b1, gamma, beta);
    k_main<<<148, 256, SMEM_MAIN>>>(diff, mask, W1, W2, b2, out, do_tail);
}